// round 7
// baseline (speedup 1.0000x reference)
#include <cuda_runtime.h>
#include <cuda_bf16.h>
#include <mma.h>
#include <math.h>
#include <stdint.h>

using namespace nvcuda;

// ---------------- problem constants ----------------
#define RESO 56
#define WS   7
#define CDIM 128
#define NHEAD 4
#define HDIM 32
#define HID  512
#define BATCH 32
#define NTOK (BATCH * RESO * RESO)      // 100352
#define NWIN (BATCH * 8 * 8)            // 2048 windows
#define TWIN 49

// ---------------- device scratch ----------------
__device__ float g_ln [(size_t)NTOK * CDIM];
__device__ float g_qkv[(size_t)NTOK * 3 * CDIM];
__device__ float g_o  [(size_t)NTOK * CDIM];
__device__ float g_x2 [(size_t)NTOK * CDIM];
__device__ float g_wT [49152 + 16384 + 65536 + 65536];

__device__ __forceinline__ float f2tf32f(float f) {
    uint32_t r; asm("cvt.rna.tf32.f32 %0, %1;" : "=r"(r) : "f"(f));
    return __uint_as_float(r);
}
__device__ __forceinline__ uint32_t smem_u32(const void* p) {
    uint32_t a;
    asm("{ .reg .u64 t; cvta.to.shared.u64 t, %1; cvt.u32.u64 %0, t; }" : "=r"(a) : "l"(p));
    return a;
}
__device__ __forceinline__ void cp_async16(uint32_t saddr, const void* gaddr) {
    asm volatile("cp.async.ca.shared.global [%0], [%1], 16;" :: "r"(saddr), "l"(gaddr));
}
#define CP_COMMIT() asm volatile("cp.async.commit_group;" ::: "memory")
#define CP_WAIT(n)  asm volatile("cp.async.wait_group %0;" :: "n"(n) : "memory")

// ---------------- fused prep: weight rounding + LN1 ----------------
#define W_QKV_N 49152
#define W_PROJ_N 16384
#define W_W1_N 65536
#define W_W2_N 65536
#define W_TOTAL (W_QKV_N + W_PROJ_N + W_W1_N + W_W2_N)
#define W_BLOCKS ((W_TOTAL + 255) / 256)          // 769
#define LN_BLOCKS ((NTOK * 32) / 256)             // 12544

__global__ void prep_kernel(const float* __restrict__ w0, const float* __restrict__ w1,
                            const float* __restrict__ w2, const float* __restrict__ w3,
                            float* __restrict__ WT,
                            const float* __restrict__ x, const float* __restrict__ g,
                            const float* __restrict__ b, float* __restrict__ out)
{
    if (blockIdx.x < W_BLOCKS) {
        int idx = blockIdx.x * 256 + threadIdx.x;
        if (idx >= W_TOTAL) return;
        float v;
        if (idx < W_QKV_N)                          v = w0[idx];
        else if (idx < W_QKV_N + W_PROJ_N)          v = w1[idx - W_QKV_N];
        else if (idx < W_QKV_N + W_PROJ_N + W_W1_N) v = w2[idx - W_QKV_N - W_PROJ_N];
        else                                        v = w3[idx - W_QKV_N - W_PROJ_N - W_W1_N];
        WT[idx] = f2tf32f(v);
        return;
    }
    int gwarp = ((blockIdx.x - W_BLOCKS) * 256 + threadIdx.x) >> 5;
    int lane  = threadIdx.x & 31;
    if (gwarp >= NTOK) return;
    float4 v = ((const float4*)(x + (size_t)gwarp * CDIM))[lane];
    float s  = v.x + v.y + v.z + v.w;
    float ss = v.x*v.x + v.y*v.y + v.z*v.z + v.w*v.w;
    #pragma unroll
    for (int off = 16; off; off >>= 1) {
        s  += __shfl_xor_sync(0xffffffffu, s,  off);
        ss += __shfl_xor_sync(0xffffffffu, ss, off);
    }
    float mean = s * (1.0f / CDIM);
    float var  = ss * (1.0f / CDIM) - mean * mean;
    float rstd = rsqrtf(var + 1e-5f);
    float4 gg = ((const float4*)g)[lane];
    float4 bb = ((const float4*)b)[lane];
    float4 o;
    o.x = f2tf32f((v.x - mean) * rstd * gg.x + bb.x);
    o.y = f2tf32f((v.y - mean) * rstd * gg.y + bb.y);
    o.z = f2tf32f((v.z - mean) * rstd * gg.z + bb.z);
    o.w = f2tf32f((v.w - mean) * rstd * gg.w + bb.w);
    ((float4*)(out + (size_t)gwarp * CDIM))[lane] = o;
}

// ---------------- WMMA tf32 GEMM (R5/R6 proven version) -------------------
enum { EPI_BIAS = 0, EPI_RES_LN2 = 3 };

#define A_STRIDE 36
#define B_STRIDE 136
#define C_STRIDE 132
#define ABUF (128 * A_STRIDE * 4)
#define BBUF (32 * B_STRIDE * 4)
#define SMEM_BYTES (2 * ABUF + 2 * BBUF)   // 71680 B

template <int EPI>
__global__ void __launch_bounds__(128, 2)
tc_gemm(const float* __restrict__ A, const float* __restrict__ B,
        const float* __restrict__ bias, const float* __restrict__ res,
        float* __restrict__ C, int N, int K,
        const float* __restrict__ lng, const float* __restrict__ lnb,
        float* __restrict__ C2)
{
    extern __shared__ char smem[];
    uint32_t sbase = smem_u32(smem);
    const int tid = threadIdx.x;
    const int wid = tid >> 5;
    const int warpM = wid & 1;
    const int warpN = wid >> 1;
    const int M0 = blockIdx.y * 128;
    const int N0 = blockIdx.x * 128;

    const float* Abase = A + (size_t)M0 * K;
    const float* Bbase = B + N0;
    const int nchunk = K >> 5;

    wmma::fragment<wmma::accumulator, 16, 16, 8, float> acc[4][4];
    #pragma unroll
    for (int i = 0; i < 4; i++)
        #pragma unroll
        for (int j = 0; j < 4; j++) wmma::fill_fragment(acc[i][j], 0.0f);

    auto load_chunk = [&](int c) {
        int buf = c & 1;
        uint32_t sa = sbase + buf * ABUF;
        uint32_t sb = sbase + 2 * ABUF + buf * BBUF;
        int k0 = c << 5;
        #pragma unroll
        for (int q = 0; q < 8; q++) {
            int e = tid + q * 128;
            int row = e >> 3, c16 = e & 7;
            cp_async16(sa + row * (A_STRIDE * 4) + c16 * 16,
                       Abase + (size_t)row * K + k0 + c16 * 4);
        }
        #pragma unroll
        for (int q = 0; q < 8; q++) {
            int e = tid + q * 128;
            int row = e >> 5, c16 = e & 31;
            cp_async16(sb + row * (B_STRIDE * 4) + c16 * 16,
                       Bbase + (size_t)(k0 + row) * N + c16 * 4);
        }
    };

    load_chunk(0);
    CP_COMMIT();

    for (int c = 0; c < nchunk; c++) {
        if (c + 1 < nchunk) {
            load_chunk(c + 1);
            CP_COMMIT();
            CP_WAIT(1);
        } else {
            CP_WAIT(0);
        }
        __syncthreads();

        int buf = c & 1;
        const float* As = (const float*)(smem + buf * ABUF);
        const float* Bs = (const float*)(smem + 2 * ABUF + buf * BBUF);
        #pragma unroll
        for (int ks = 0; ks < 4; ks++) {
            wmma::fragment<wmma::matrix_a, 16, 16, 8, wmma::precision::tf32, wmma::row_major> af[4];
            wmma::fragment<wmma::matrix_b, 16, 16, 8, wmma::precision::tf32, wmma::row_major> bf[4];
            #pragma unroll
            for (int i = 0; i < 4; i++)
                wmma::load_matrix_sync(af[i],
                    As + (warpM * 64 + i * 16) * A_STRIDE + ks * 8, A_STRIDE);
            #pragma unroll
            for (int j = 0; j < 4; j++)
                wmma::load_matrix_sync(bf[j],
                    Bs + (ks * 8) * B_STRIDE + warpN * 64 + j * 16, B_STRIDE);
            #pragma unroll
            for (int i = 0; i < 4; i++)
                #pragma unroll
                for (int j = 0; j < 4; j++)
                    wmma::mma_sync(acc[i][j], af[i], bf[j], acc[i][j]);
        }
        __syncthreads();
    }

    float* Cs = (float*)smem;
    #pragma unroll
    for (int i = 0; i < 4; i++)
        #pragma unroll
        for (int j = 0; j < 4; j++)
            wmma::store_matrix_sync(
                Cs + (warpM * 64 + i * 16) * C_STRIDE + warpN * 64 + j * 16,
                acc[i][j], C_STRIDE, wmma::mem_row_major);
    __syncthreads();

    #pragma unroll
    for (int e0 = 0; e0 < 32; e0++) {
        int e = tid + e0 * 128;
        int row = e >> 5;
        int c4  = (e & 31) * 4;
        size_t roff = (size_t)(M0 + row) * N + N0 + c4;
        float v[4];
        #pragma unroll
        for (int q = 0; q < 4; q++) {
            float t = Cs[row * C_STRIDE + c4 + q] + __ldg(bias + N0 + c4 + q);
            if (EPI == EPI_RES_LN2) t += res[roff + q];
            v[q] = t;
        }
        if (EPI == EPI_RES_LN2) {
            float s  = v[0] + v[1] + v[2] + v[3];
            float ss = v[0]*v[0] + v[1]*v[1] + v[2]*v[2] + v[3]*v[3];
            #pragma unroll
            for (int off = 16; off; off >>= 1) {
                s  += __shfl_xor_sync(0xffffffffu, s,  off);
                ss += __shfl_xor_sync(0xffffffffu, ss, off);
            }
            float mean = s * (1.0f / CDIM);
            float var  = ss * (1.0f / CDIM) - mean * mean;
            float rstd = rsqrtf(var + 1e-5f);
            float lnv[4];
            #pragma unroll
            for (int q = 0; q < 4; q++)
                lnv[q] = f2tf32f((v[q] - mean) * rstd * __ldg(lng + c4 + q)
                                 + __ldg(lnb + c4 + q));
            *(float4*)(C2 + roff) = *(float4*)lnv;
        }
        *(float4*)(C + roff) = *(float4*)v;
    }
}

// ---------------- fused MLP: out = x2 + gelu(ln2@w1+b1)@w2 + b2 ------------
// One CTA per 128 tokens. 256 threads, 8 warps as 4M x 2N.
// Hidden dim processed in 8 chunks of 64; h1 never leaves smem.
#define FM_AS   0                       // 128 x 132 floats (ln2 tile / out staging)
#define FM_W1   16896                   // 2 x (128 x 72)
#define FM_W1SZ 9216
#define FM_H1   35328                   // 128 x 68
#define FM_W2   44032                   // 64 x 136
#define FM_SMEM 210944                  // bytes

__global__ void __launch_bounds__(256, 1)
fused_mlp(const float* __restrict__ A, const float* __restrict__ w1,
          const float* __restrict__ b1, const float* __restrict__ w2,
          const float* __restrict__ b2, const float* __restrict__ res,
          float* __restrict__ out)
{
    extern __shared__ float sm[];
    uint32_t sbase = smem_u32(sm);
    const int tid = threadIdx.x;
    const int wid = tid >> 5;
    const int warpM = wid & 3;          // 0..3 -> 32 rows
    const int warpN = wid >> 2;         // 0..1
    const int M0 = blockIdx.x * 128;
    const float* Abase = A + (size_t)M0 * CDIM;

    wmma::fragment<wmma::accumulator, 16, 16, 8, float> acc2[2][4];
    #pragma unroll
    for (int i = 0; i < 2; i++)
        #pragma unroll
        for (int j = 0; j < 4; j++) wmma::fill_fragment(acc2[i][j], 0.0f);

    // prologue loads: A tile, w1 chunk 0, w2 chunk 0
    #pragma unroll
    for (int q = 0; q < 16; q++) {      // 4096 16B chunks of A
        int e = tid + q * 256;
        int row = e >> 5, c16 = e & 31;
        cp_async16(sbase + (FM_AS + row * 132 + c16 * 4) * 4,
                   Abase + (size_t)row * CDIM + c16 * 4);
    }
    CP_COMMIT();
    #pragma unroll
    for (int q = 0; q < 8; q++) {       // w1 chunk 0: 128 rows x 16 chunks
        int e = tid + q * 256;
        int row = e >> 4, c16 = e & 15;
        cp_async16(sbase + (FM_W1 + row * 72 + c16 * 4) * 4,
                   w1 + (size_t)row * HID + c16 * 4);
    }
    CP_COMMIT();
    #pragma unroll
    for (int q = 0; q < 8; q++) {       // w2 chunk 0: 64 rows x 32 chunks
        int e = tid + q * 256;
        int row = e >> 5, c16 = e & 31;
        cp_async16(sbase + (FM_W2 + row * 136 + c16 * 4) * 4,
                   w2 + (size_t)row * CDIM + c16 * 4);
    }
    CP_COMMIT();

    for (int c = 0; c < 8; c++) {
        // need A + w1[c]; w2[c] may still be pending (1 group)
        CP_WAIT(1);
        __syncthreads();

        // GEMM1: acc1 = As @ w1chunk   (128x64x128)
        wmma::fragment<wmma::accumulator, 16, 16, 8, float> acc1[2][2];
        #pragma unroll
        for (int i = 0; i < 2; i++)
            #pragma unroll
            for (int j = 0; j < 2; j++) wmma::fill_fragment(acc1[i][j], 0.0f);
        const float* W1s = sm + FM_W1 + (c & 1) * FM_W1SZ;
        #pragma unroll
        for (int ks = 0; ks < 16; ks++) {
            wmma::fragment<wmma::matrix_a, 16, 16, 8, wmma::precision::tf32, wmma::row_major> af[2];
            wmma::fragment<wmma::matrix_b, 16, 16, 8, wmma::precision::tf32, wmma::row_major> bf[2];
            #pragma unroll
            for (int i = 0; i < 2; i++)
                wmma::load_matrix_sync(af[i], sm + FM_AS + (warpM * 32 + i * 16) * 132 + ks * 8, 132);
            #pragma unroll
            for (int j = 0; j < 2; j++)
                wmma::load_matrix_sync(bf[j], W1s + (ks * 8) * 72 + warpN * 32 + j * 16, 72);
            #pragma unroll
            for (int i = 0; i < 2; i++)
                #pragma unroll
                for (int j = 0; j < 2; j++)
                    wmma::mma_sync(acc1[i][j], af[i], bf[j], acc1[i][j]);
        }

        // prefetch w1[c+1] (overlaps gelu + GEMM2)
        if (c < 7) {
            uint32_t dst = sbase + (FM_W1 + ((c + 1) & 1) * FM_W1SZ) * 4;
            #pragma unroll
            for (int q = 0; q < 8; q++) {
                int e = tid + q * 256;
                int row = e >> 4, c16 = e & 15;
                cp_async16(dst + (row * 72 + c16 * 4) * 4,
                           w1 + (size_t)row * HID + (c + 1) * 64 + c16 * 4);
            }
            CP_COMMIT();
        }

        // stage acc1 -> H1 (raw)
        #pragma unroll
        for (int i = 0; i < 2; i++)
            #pragma unroll
            for (int j = 0; j < 2; j++)
                wmma::store_matrix_sync(
                    sm + FM_H1 + (warpM * 32 + i * 16) * 68 + warpN * 32 + j * 16,
                    acc1[i][j], 68, wmma::mem_row_major);
        __syncthreads();

        // gelu + bias + tf32-round in place
        #pragma unroll
        for (int q = 0; q < 8; q++) {
            int e = tid + q * 256;
            int row = e >> 4, c4 = (e & 15) * 4;
            float* hp = sm + FM_H1 + row * 68 + c4;
            float4 h = *(float4*)hp;
            float hv[4] = {h.x, h.y, h.z, h.w};
            #pragma unroll
            for (int u = 0; u < 4; u++) {
                float t = hv[u] + __ldg(b1 + c * 64 + c4 + u);
                t = 0.5f * t * (1.0f + erff(t * 0.70710678118654752f));
                hv[u] = f2tf32f(t);
            }
            *(float4*)hp = make_float4(hv[0], hv[1], hv[2], hv[3]);
        }
        __syncthreads();

        // ensure w2[c] landed (w1[c+1] may still be in flight)
        if (c < 7) { CP_WAIT(1); } else { CP_WAIT(0); }
        __syncthreads();

        // GEMM2: acc2 += h1chunk @ w2chunk  (128x128x64)
        #pragma unroll
        for (int ks = 0; ks < 8; ks++) {
            wmma::fragment<wmma::matrix_a, 16, 16, 8, wmma::precision::tf32, wmma::row_major> af2[2];
            wmma::fragment<wmma::matrix_b, 16, 16, 8, wmma::precision::tf32, wmma::row_major> bf2[4];
            #pragma unroll
            for (int i = 0; i < 2; i++)
                wmma::load_matrix_sync(af2[i], sm + FM_H1 + (warpM * 32 + i * 16) * 68 + ks * 8, 68);
            #pragma unroll
            for (int j = 0; j < 4; j++)
                wmma::load_matrix_sync(bf2[j], sm + FM_W2 + (ks * 8) * 136 + warpN * 64 + j * 16, 136);
            #pragma unroll
            for (int i = 0; i < 2; i++)
                #pragma unroll
                for (int j = 0; j < 4; j++)
                    wmma::mma_sync(acc2[i][j], af2[i], bf2[j], acc2[i][j]);
        }
        __syncthreads();

        // prefetch w2[c+1] (w2buf free now; overlaps next GEMM1)
        if (c < 7) {
            #pragma unroll
            for (int q = 0; q < 8; q++) {
                int e = tid + q * 256;
                int row = e >> 5, c16 = e & 31;
                cp_async16(sbase + (FM_W2 + row * 136 + c16 * 4) * 4,
                           w2 + (size_t)((c + 1) * 64 + row) * CDIM + c16 * 4);
            }
            CP_COMMIT();
        }
    }

    // final epilogue: stage acc2 into As region, add bias2 + residual
    #pragma unroll
    for (int i = 0; i < 2; i++)
        #pragma unroll
        for (int j = 0; j < 4; j++)
            wmma::store_matrix_sync(
                sm + FM_AS + (warpM * 32 + i * 16) * 132 + warpN * 64 + j * 16,
                acc2[i][j], 132, wmma::mem_row_major);
    __syncthreads();

    #pragma unroll
    for (int q = 0; q < 16; q++) {
        int e = tid + q * 256;
        int row = e >> 5, c4 = (e & 31) * 4;
        size_t roff = (size_t)(M0 + row) * CDIM + c4;
        float4 r = *(const float4*)(res + roff);
        float v[4];
        #pragma unroll
        for (int u = 0; u < 4; u++)
            v[u] = sm[FM_AS + row * 132 + c4 + u] + __ldg(b2 + c4 + u);
        v[0] += r.x; v[1] += r.y; v[2] += r.z; v[3] += r.w;
        *(float4*)(out + roff) = *(float4*)v;
    }
}

// ---------------- windowed attention (R6 proven version) ----------
#define QS_STRIDE 36
#define S_STRIDE  50

__global__ __launch_bounds__(256)
void attn_kernel(const float* __restrict__ qkv, float* __restrict__ o)
{
    int blk  = blockIdx.x;
    int head = blk & 3;
    int w    = blk >> 2;
    int bimg = w >> 6;
    int win  = w & 63;
    int wr   = win >> 3, wc = win & 7;

    __shared__ int tok[TWIN];
    __shared__ __align__(16) float qs[52 * QS_STRIDE];
    __shared__ __align__(16) float ks[50 * QS_STRIDE];
    __shared__ __align__(16) float vs[49 * QS_STRIDE];
    __shared__ __align__(16) float S[52 * S_STRIDE];

    int tid = threadIdx.x;
    if (tid < TWIN) {
        int r = tid / WS, c = tid - r * WS;
        tok[tid] = bimg * (RESO * RESO) + (wr * WS + r) * RESO + (wc * WS + c);
    }
    if (tid < 3 * QS_STRIDE) qs[49 * QS_STRIDE + tid] = 0.0f;
    if (tid >= 128 && tid < 128 + QS_STRIDE) ks[49 * QS_STRIDE + (tid - 128)] = 0.0f;
    __syncthreads();

    for (int idx = tid; idx < TWIN * HDIM * 3; idx += 256) {
        int which = idx / (TWIN * HDIM);
        int rem   = idx - which * (TWIN * HDIM);
        int t = rem >> 5, d = rem & 31;
        float val = qkv[(size_t)tok[t] * (3 * CDIM) + which * CDIM + head * HDIM + d];
        float* dst = (which == 0) ? qs : (which == 1) ? ks : vs;
        dst[t * QS_STRIDE + d] = val;
    }
    __syncthreads();

    const float scale = 0.17677669529663687f;
    for (int t = tid; t < 13 * 25; t += 256) {
        int qg = t / 25, kg = t - qg * 25;
        int qi0 = qg * 4, ki0 = kg * 2;
        float a[4][2];
        #pragma unroll
        for (int i = 0; i < 4; i++) { a[i][0] = 0.0f; a[i][1] = 0.0f; }
        #pragma unroll
        for (int dq = 0; dq < 8; dq++) {
            float4 k0 = *(const float4*)&ks[ki0 * QS_STRIDE + 4 * dq];
            float4 k1 = *(const float4*)&ks[(ki0 + 1) * QS_STRIDE + 4 * dq];
            #pragma unroll
            for (int i = 0; i < 4; i++) {
                float4 q = *(const float4*)&qs[(qi0 + i) * QS_STRIDE + 4 * dq];
                a[i][0] = fmaf(q.x, k0.x, fmaf(q.y, k0.y, fmaf(q.z, k0.z, fmaf(q.w, k0.w, a[i][0]))));
                a[i][1] = fmaf(q.x, k1.x, fmaf(q.y, k1.y, fmaf(q.z, k1.z, fmaf(q.w, k1.w, a[i][1]))));
            }
        }
        #pragma unroll
        for (int i = 0; i < 4; i++)
            if (qi0 + i < TWIN)
                #pragma unroll
                for (int j = 0; j < 2; j++)
                    if (ki0 + j < TWIN)
                        S[(qi0 + i) * S_STRIDE + ki0 + j] = a[i][j] * scale;
    }
    __syncthreads();

    int warp = tid >> 5, lane = tid & 31;
    for (int row = warp; row < TWIN; row += 8) {
        float v0 = S[row * S_STRIDE + lane];
        float v1 = (lane + 32 < TWIN) ? S[row * S_STRIDE + lane + 32] : -3.4e38f;
        float m = fmaxf(v0, v1);
        #pragma unroll
        for (int off = 16; off; off >>= 1)
            m = fmaxf(m, __shfl_xor_sync(0xffffffffu, m, off));
        float e0 = __expf(v0 - m);
        float e1 = (lane + 32 < TWIN) ? __expf(v1 - m) : 0.0f;
        float s = e0 + e1;
        #pragma unroll
        for (int off = 16; off; off >>= 1)
            s += __shfl_xor_sync(0xffffffffu, s, off);
        float inv = 1.0f / s;
        S[row * S_STRIDE + lane] = e0 * inv;
        if (lane + 32 < TWIN) S[row * S_STRIDE + lane + 32] = e1 * inv;
    }
    __syncthreads();

    for (int t = tid; t < 13 * 16; t += 256) {
        int qg = t / 16, dp = t - qg * 16;
        int qi0 = qg * 4, d = dp * 2;
        float ax0 = 0, ay0 = 0, ax1 = 0, ay1 = 0,
              ax2 = 0, ay2 = 0, ax3 = 0, ay3 = 0;
        for (int ki = 0; ki < TWIN; ki++) {
            float2 vv = *(const float2*)&vs[ki * QS_STRIDE + d];
            float s0 = S[(qi0 + 0) * S_STRIDE + ki];
            float s1 = S[(qi0 + 1) * S_STRIDE + ki];
            float s2 = S[(qi0 + 2) * S_STRIDE + ki];
            float s3 = S[(qi0 + 3) * S_STRIDE + ki];
            ax0 = fmaf(s0, vv.x, ax0); ay0 = fmaf(s0, vv.y, ay0);
            ax1 = fmaf(s1, vv.x, ax1); ay1 = fmaf(s1, vv.y, ay1);
            ax2 = fmaf(s2, vv.x, ax2); ay2 = fmaf(s2, vv.y, ay2);
            ax3 = fmaf(s3, vv.x, ax3); ay3 = fmaf(s3, vv.y, ay3);
        }
        float axs[4] = {ax0, ax1, ax2, ax3};
        float ays[4] = {ay0, ay1, ay2, ay3};
        #pragma unroll
        for (int i = 0; i < 4; i++) {
            if (qi0 + i < TWIN) {
                float* dst = o + (size_t)tok[qi0 + i] * CDIM + head * HDIM + d;
                dst[0] = f2tf32f(axs[i]);
                dst[1] = f2tf32f(ays[i]);
            }
        }
    }
}

// ---------------- launch ----------------
extern "C" void kernel_launch(void* const* d_in, const int* in_sizes, int n_in,
                              void* d_out, int out_size)
{
    const float* x      = (const float*)d_in[0];
    const float* ln1_g  = (const float*)d_in[1];
    const float* ln1_b  = (const float*)d_in[2];
    const float* qkv_w  = (const float*)d_in[3];
    const float* qkv_b  = (const float*)d_in[4];
    const float* proj_w = (const float*)d_in[5];
    const float* proj_b = (const float*)d_in[6];
    const float* ln2_g  = (const float*)d_in[7];
    const float* ln2_b  = (const float*)d_in[8];
    const float* mlp_w1 = (const float*)d_in[9];
    const float* mlp_b1 = (const float*)d_in[10];
    const float* mlp_w2 = (const float*)d_in[11];
    const float* mlp_b2 = (const float*)d_in[12];
    float* out = (float*)d_out;

    float *p_ln, *p_qkv, *p_o, *p_x2, *p_wT;
    cudaGetSymbolAddress((void**)&p_ln,  g_ln);
    cudaGetSymbolAddress((void**)&p_qkv, g_qkv);
    cudaGetSymbolAddress((void**)&p_o,   g_o);
    cudaGetSymbolAddress((void**)&p_x2,  g_x2);
    cudaGetSymbolAddress((void**)&p_wT,  g_wT);
    float* wt_qkv  = p_wT;
    float* wt_proj = p_wT + W_QKV_N;
    float* wt_w1   = p_wT + W_QKV_N + W_PROJ_N;
    float* wt_w2   = p_wT + W_QKV_N + W_PROJ_N + W_W1_N;

    cudaFuncSetAttribute(tc_gemm<EPI_BIAS>,    cudaFuncAttributeMaxDynamicSharedMemorySize, SMEM_BYTES);
    cudaFuncSetAttribute(tc_gemm<EPI_RES_LN2>, cudaFuncAttributeMaxDynamicSharedMemorySize, SMEM_BYTES);
    cudaFuncSetAttribute(fused_mlp,            cudaFuncAttributeMaxDynamicSharedMemorySize, FM_SMEM);

    const int MT = NTOK / 128;  // 784

    // 0. fused prep: weight rounding + LN1
    prep_kernel<<<W_BLOCKS + LN_BLOCKS, 256>>>(qkv_w, proj_w, mlp_w1, mlp_w2, p_wT,
                                               x, ln1_g, ln1_b, p_ln);
    // 1. QKV = ln1 @ qkv_w + qkv_b
    tc_gemm<EPI_BIAS><<<dim3(3, MT), 128, SMEM_BYTES>>>(
        p_ln, wt_qkv, qkv_b, nullptr, p_qkv, 3 * CDIM, CDIM, nullptr, nullptr, nullptr);
    // 2. attention
    attn_kernel<<<NWIN * NHEAD, 256>>>(p_qkv, p_o);
    // 3. x2 = x + proj(o); fused LN2 -> p_ln
    tc_gemm<EPI_RES_LN2><<<dim3(1, MT), 128, SMEM_BYTES>>>(
        p_o, wt_proj, proj_b, x, p_x2, CDIM, CDIM, ln2_g, ln2_b, p_ln);
    // 4. fused MLP: out = x2 + gelu(ln2@w1+b1)@w2 + b2
    fused_mlp<<<MT, 256, FM_SMEM>>>(p_ln, wt_w1, mlp_b1, wt_w2, mlp_b2, p_x2, out);
}

// round 8
// speedup vs baseline: 1.0511x; 1.0511x over previous
#include <cuda_runtime.h>
#include <cuda_bf16.h>
#include <mma.h>
#include <math.h>
#include <stdint.h>

using namespace nvcuda;

// ---------------- problem constants ----------------
#define RESO 56
#define WS   7
#define CDIM 128
#define NHEAD 4
#define HDIM 32
#define HID  512
#define BATCH 32
#define NTOK (BATCH * RESO * RESO)      // 100352
#define NWIN (BATCH * 8 * 8)            // 2048 windows
#define TWIN 49

// ---------------- device scratch ----------------
__device__ float g_qkv[(size_t)NTOK * 3 * CDIM];
__device__ float g_o  [(size_t)NTOK * CDIM];
__device__ float g_x2 [(size_t)NTOK * CDIM];
__device__ float g_h1 [(size_t)NTOK * HID];
__device__ float g_wT [49152 + 16384 + 65536 + 65536];

__device__ __forceinline__ float f2tf32f(float f) {
    uint32_t r; asm("cvt.rna.tf32.f32 %0, %1;" : "=r"(r) : "f"(f));
    return __uint_as_float(r);
}
__device__ __forceinline__ uint32_t smem_u32(const void* p) {
    uint32_t a;
    asm("{ .reg .u64 t; cvta.to.shared.u64 t, %1; cvt.u32.u64 %0, t; }" : "=r"(a) : "l"(p));
    return a;
}
__device__ __forceinline__ void cp_async16(uint32_t saddr, const void* gaddr) {
    asm volatile("cp.async.ca.shared.global [%0], [%1], 16;" :: "r"(saddr), "l"(gaddr));
}
#define CP_COMMIT() asm volatile("cp.async.commit_group;" ::: "memory")
#define CP_WAIT(n)  asm volatile("cp.async.wait_group %0;" :: "n"(n) : "memory")

// ---------------- prep: weight rounding only ----------------
#define W_QKV_N 49152
#define W_PROJ_N 16384
#define W_W1_N 65536
#define W_W2_N 65536
#define W_TOTAL (W_QKV_N + W_PROJ_N + W_W1_N + W_W2_N)

__global__ void prep_kernel(const float* __restrict__ w0, const float* __restrict__ w1,
                            const float* __restrict__ w2, const float* __restrict__ w3,
                            float* __restrict__ WT)
{
    int idx = blockIdx.x * 256 + threadIdx.x;
    if (idx >= W_TOTAL) return;
    float v;
    if (idx < W_QKV_N)                          v = w0[idx];
    else if (idx < W_QKV_N + W_PROJ_N)          v = w1[idx - W_QKV_N];
    else if (idx < W_QKV_N + W_PROJ_N + W_W1_N) v = w2[idx - W_QKV_N - W_PROJ_N];
    else                                        v = w3[idx - W_QKV_N - W_PROJ_N - W_W1_N];
    WT[idx] = f2tf32f(v);
}

// ---------------- shared GEMM config ----------------
enum { EPI_BIAS = 0, EPI_BIAS_RES = 1, EPI_GELU = 2 };

#define A_STRIDE 36
#define B_STRIDE 136
#define C_STRIDE 132
#define ABUF (128 * A_STRIDE * 4)
#define BBUF (32 * B_STRIDE * 4)
#define SMEM_BYTES (2 * ABUF + 2 * BBUF)       // 71680 B (streaming kernel)

// lnA kernel: A resident (128x132) + B double buffer
#define LA_AS    0
#define LA_ABYTES (128 * 132 * 4)              // 67584
#define LA_B     LA_ABYTES
#define LA_SMEM  (LA_ABYTES + 2 * BBUF)        // 102400 B

// ---------------- streaming WMMA tf32 GEMM (R5/R6 proven) -----------------
template <int EPI>
__global__ void __launch_bounds__(128, 2)
tc_gemm(const float* __restrict__ A, const float* __restrict__ B,
        const float* __restrict__ bias, const float* __restrict__ res,
        float* __restrict__ C, int N, int K)
{
    extern __shared__ char smem[];
    uint32_t sbase = smem_u32(smem);
    const int tid = threadIdx.x;
    const int wid = tid >> 5;
    const int warpM = wid & 1;
    const int warpN = wid >> 1;
    const int M0 = blockIdx.y * 128;
    const int N0 = blockIdx.x * 128;

    const float* Abase = A + (size_t)M0 * K;
    const float* Bbase = B + N0;
    const int nchunk = K >> 5;

    wmma::fragment<wmma::accumulator, 16, 16, 8, float> acc[4][4];
    #pragma unroll
    for (int i = 0; i < 4; i++)
        #pragma unroll
        for (int j = 0; j < 4; j++) wmma::fill_fragment(acc[i][j], 0.0f);

    auto load_chunk = [&](int c) {
        int buf = c & 1;
        uint32_t sa = sbase + buf * ABUF;
        uint32_t sb = sbase + 2 * ABUF + buf * BBUF;
        int k0 = c << 5;
        #pragma unroll
        for (int q = 0; q < 8; q++) {
            int e = tid + q * 128;
            int row = e >> 3, c16 = e & 7;
            cp_async16(sa + row * (A_STRIDE * 4) + c16 * 16,
                       Abase + (size_t)row * K + k0 + c16 * 4);
        }
        #pragma unroll
        for (int q = 0; q < 8; q++) {
            int e = tid + q * 128;
            int row = e >> 5, c16 = e & 31;
            cp_async16(sb + row * (B_STRIDE * 4) + c16 * 16,
                       Bbase + (size_t)(k0 + row) * N + c16 * 4);
        }
    };

    load_chunk(0);
    CP_COMMIT();

    for (int c = 0; c < nchunk; c++) {
        if (c + 1 < nchunk) {
            load_chunk(c + 1);
            CP_COMMIT();
            CP_WAIT(1);
        } else {
            CP_WAIT(0);
        }
        __syncthreads();

        int buf = c & 1;
        const float* As = (const float*)(smem + buf * ABUF);
        const float* Bs = (const float*)(smem + 2 * ABUF + buf * BBUF);
        #pragma unroll
        for (int ks = 0; ks < 4; ks++) {
            wmma::fragment<wmma::matrix_a, 16, 16, 8, wmma::precision::tf32, wmma::row_major> af[4];
            wmma::fragment<wmma::matrix_b, 16, 16, 8, wmma::precision::tf32, wmma::row_major> bf[4];
            #pragma unroll
            for (int i = 0; i < 4; i++)
                wmma::load_matrix_sync(af[i],
                    As + (warpM * 64 + i * 16) * A_STRIDE + ks * 8, A_STRIDE);
            #pragma unroll
            for (int j = 0; j < 4; j++)
                wmma::load_matrix_sync(bf[j],
                    Bs + (ks * 8) * B_STRIDE + warpN * 64 + j * 16, B_STRIDE);
            #pragma unroll
            for (int i = 0; i < 4; i++)
                #pragma unroll
                for (int j = 0; j < 4; j++)
                    wmma::mma_sync(acc[i][j], af[i], bf[j], acc[i][j]);
        }
        __syncthreads();
    }

    float* Cs = (float*)smem;
    #pragma unroll
    for (int i = 0; i < 4; i++)
        #pragma unroll
        for (int j = 0; j < 4; j++)
            wmma::store_matrix_sync(
                Cs + (warpM * 64 + i * 16) * C_STRIDE + warpN * 64 + j * 16,
                acc[i][j], C_STRIDE, wmma::mem_row_major);
    __syncthreads();

    #pragma unroll
    for (int e0 = 0; e0 < 32; e0++) {
        int e = tid + e0 * 128;
        int row = e >> 5;
        int c4  = (e & 31) * 4;
        size_t roff = (size_t)(M0 + row) * N + N0 + c4;
        float v[4];
        #pragma unroll
        for (int q = 0; q < 4; q++) {
            float t = Cs[row * C_STRIDE + c4 + q] + __ldg(bias + N0 + c4 + q);
            if (EPI == EPI_BIAS_RES) t += res[roff + q];
            v[q] = t;
        }
        *(float4*)(C + roff) = *(float4*)v;
    }
}

// ------- resident-A GEMM with in-smem LayerNorm: C = epi(LN(X) @ B + bias) -
// K = CDIM = 128 fixed. A tile loaded once, LN'd in place (tf32-rounded).
template <int EPI>
__global__ void __launch_bounds__(128, 2)
tc_gemm_lnA(const float* __restrict__ X, const float* __restrict__ B,
            const float* __restrict__ bias,
            const float* __restrict__ lng, const float* __restrict__ lnb,
            float* __restrict__ C, int N)
{
    extern __shared__ char smem[];
    float* sm = (float*)smem;
    uint32_t sbase = smem_u32(smem);
    const int tid = threadIdx.x;
    const int wid = tid >> 5;
    const int lane = tid & 31;
    const int warpM = wid & 1;
    const int warpN = wid >> 1;
    const int M0 = blockIdx.y * 128;
    const int N0 = blockIdx.x * 128;
    const float* Bbase = B + N0;

    wmma::fragment<wmma::accumulator, 16, 16, 8, float> acc[4][4];
    #pragma unroll
    for (int i = 0; i < 4; i++)
        #pragma unroll
        for (int j = 0; j < 4; j++) wmma::fill_fragment(acc[i][j], 0.0f);

    // load X tile (128 x 128) into As (stride 132)
    #pragma unroll
    for (int q = 0; q < 32; q++) {
        int e = tid + q * 128;
        int row = e >> 5, c16 = e & 31;
        cp_async16(sbase + (row * 132 + c16 * 4) * 4,
                   X + (size_t)(M0 + row) * CDIM + c16 * 4);
    }
    CP_COMMIT();
    // B chunk 0
    auto load_b = [&](int c) {
        uint32_t sb = sbase + LA_B + (c & 1) * BBUF;
        int k0 = c << 5;
        #pragma unroll
        for (int q = 0; q < 8; q++) {
            int e = tid + q * 128;
            int row = e >> 5, c16 = e & 31;
            cp_async16(sb + row * (B_STRIDE * 4) + c16 * 16,
                       Bbase + (size_t)(k0 + row) * N + c16 * 4);
        }
    };
    load_b(0);
    CP_COMMIT();

    CP_WAIT(1);                 // X tile landed (B0 may be in flight)
    __syncthreads();

    // LayerNorm in place: one warp per row, 32 rows per warp
    float4 gg = __ldg((const float4*)lng + lane);
    float4 bb = __ldg((const float4*)lnb + lane);
    for (int r = wid; r < 128; r += 4) {
        float4 v = *(float4*)&sm[r * 132 + lane * 4];
        float s  = v.x + v.y + v.z + v.w;
        float ss = v.x*v.x + v.y*v.y + v.z*v.z + v.w*v.w;
        #pragma unroll
        for (int off = 16; off; off >>= 1) {
            s  += __shfl_xor_sync(0xffffffffu, s,  off);
            ss += __shfl_xor_sync(0xffffffffu, ss, off);
        }
        float mean = s * (1.0f / CDIM);
        float var  = ss * (1.0f / CDIM) - mean * mean;
        float rstd = rsqrtf(var + 1e-5f);
        float4 o;
        o.x = f2tf32f((v.x - mean) * rstd * gg.x + bb.x);
        o.y = f2tf32f((v.y - mean) * rstd * gg.y + bb.y);
        o.z = f2tf32f((v.z - mean) * rstd * gg.z + bb.z);
        o.w = f2tf32f((v.w - mean) * rstd * gg.w + bb.w);
        *(float4*)&sm[r * 132 + lane * 4] = o;
    }
    __syncthreads();

    // mainloop: stream B only; A resident
    for (int c = 0; c < 4; c++) {
        if (c < 3) {
            load_b(c + 1);
            CP_COMMIT();
            CP_WAIT(1);
        } else {
            CP_WAIT(0);
        }
        __syncthreads();
        const float* Bs = sm + (LA_B >> 2) + (c & 1) * (BBUF >> 2);
        #pragma unroll
        for (int ks = 0; ks < 4; ks++) {
            wmma::fragment<wmma::matrix_a, 16, 16, 8, wmma::precision::tf32, wmma::row_major> af[4];
            wmma::fragment<wmma::matrix_b, 16, 16, 8, wmma::precision::tf32, wmma::row_major> bf[4];
            #pragma unroll
            for (int i = 0; i < 4; i++)
                wmma::load_matrix_sync(af[i],
                    sm + (warpM * 64 + i * 16) * 132 + c * 32 + ks * 8, 132);
            #pragma unroll
            for (int j = 0; j < 4; j++)
                wmma::load_matrix_sync(bf[j],
                    Bs + (ks * 8) * B_STRIDE + warpN * 64 + j * 16, B_STRIDE);
            #pragma unroll
            for (int i = 0; i < 4; i++)
                #pragma unroll
                for (int j = 0; j < 4; j++)
                    wmma::mma_sync(acc[i][j], af[i], bf[j], acc[i][j]);
        }
        __syncthreads();
    }

    // epilogue: reuse As region for staging
    #pragma unroll
    for (int i = 0; i < 4; i++)
        #pragma unroll
        for (int j = 0; j < 4; j++)
            wmma::store_matrix_sync(
                sm + (warpM * 64 + i * 16) * C_STRIDE + warpN * 64 + j * 16,
                acc[i][j], C_STRIDE, wmma::mem_row_major);
    __syncthreads();

    #pragma unroll
    for (int e0 = 0; e0 < 32; e0++) {
        int e = tid + e0 * 128;
        int row = e >> 5;
        int c4  = (e & 31) * 4;
        size_t roff = (size_t)(M0 + row) * N + N0 + c4;
        float v[4];
        #pragma unroll
        for (int q = 0; q < 4; q++) {
            float t = sm[row * C_STRIDE + c4 + q] + __ldg(bias + N0 + c4 + q);
            if (EPI == EPI_GELU) {
                t = 0.5f * t * (1.0f + erff(t * 0.70710678118654752f));
                t = f2tf32f(t);
            }
            v[q] = t;
        }
        *(float4*)(C + roff) = *(float4*)v;
    }
}

// ---------------- windowed attention (R6 proven version) ----------
#define QS_STRIDE 36
#define S_STRIDE  50

__global__ __launch_bounds__(256)
void attn_kernel(const float* __restrict__ qkv, float* __restrict__ o)
{
    int blk  = blockIdx.x;
    int head = blk & 3;
    int w    = blk >> 2;
    int bimg = w >> 6;
    int win  = w & 63;
    int wr   = win >> 3, wc = win & 7;

    __shared__ int tok[TWIN];
    __shared__ __align__(16) float qs[52 * QS_STRIDE];
    __shared__ __align__(16) float ks[50 * QS_STRIDE];
    __shared__ __align__(16) float vs[49 * QS_STRIDE];
    __shared__ __align__(16) float S[52 * S_STRIDE];

    int tid = threadIdx.x;
    if (tid < TWIN) {
        int r = tid / WS, c = tid - r * WS;
        tok[tid] = bimg * (RESO * RESO) + (wr * WS + r) * RESO + (wc * WS + c);
    }
    if (tid < 3 * QS_STRIDE) qs[49 * QS_STRIDE + tid] = 0.0f;
    if (tid >= 128 && tid < 128 + QS_STRIDE) ks[49 * QS_STRIDE + (tid - 128)] = 0.0f;
    __syncthreads();

    for (int idx = tid; idx < TWIN * HDIM * 3; idx += 256) {
        int which = idx / (TWIN * HDIM);
        int rem   = idx - which * (TWIN * HDIM);
        int t = rem >> 5, d = rem & 31;
        float val = qkv[(size_t)tok[t] * (3 * CDIM) + which * CDIM + head * HDIM + d];
        float* dst = (which == 0) ? qs : (which == 1) ? ks : vs;
        dst[t * QS_STRIDE + d] = val;
    }
    __syncthreads();

    const float scale = 0.17677669529663687f;
    for (int t = tid; t < 13 * 25; t += 256) {
        int qg = t / 25, kg = t - qg * 25;
        int qi0 = qg * 4, ki0 = kg * 2;
        float a[4][2];
        #pragma unroll
        for (int i = 0; i < 4; i++) { a[i][0] = 0.0f; a[i][1] = 0.0f; }
        #pragma unroll
        for (int dq = 0; dq < 8; dq++) {
            float4 k0 = *(const float4*)&ks[ki0 * QS_STRIDE + 4 * dq];
            float4 k1 = *(const float4*)&ks[(ki0 + 1) * QS_STRIDE + 4 * dq];
            #pragma unroll
            for (int i = 0; i < 4; i++) {
                float4 q = *(const float4*)&qs[(qi0 + i) * QS_STRIDE + 4 * dq];
                a[i][0] = fmaf(q.x, k0.x, fmaf(q.y, k0.y, fmaf(q.z, k0.z, fmaf(q.w, k0.w, a[i][0]))));
                a[i][1] = fmaf(q.x, k1.x, fmaf(q.y, k1.y, fmaf(q.z, k1.z, fmaf(q.w, k1.w, a[i][1]))));
            }
        }
        #pragma unroll
        for (int i = 0; i < 4; i++)
            if (qi0 + i < TWIN)
                #pragma unroll
                for (int j = 0; j < 2; j++)
                    if (ki0 + j < TWIN)
                        S[(qi0 + i) * S_STRIDE + ki0 + j] = a[i][j] * scale;
    }
    __syncthreads();

    int warp = tid >> 5, lane = tid & 31;
    for (int row = warp; row < TWIN; row += 8) {
        float v0 = S[row * S_STRIDE + lane];
        float v1 = (lane + 32 < TWIN) ? S[row * S_STRIDE + lane + 32] : -3.4e38f;
        float m = fmaxf(v0, v1);
        #pragma unroll
        for (int off = 16; off; off >>= 1)
            m = fmaxf(m, __shfl_xor_sync(0xffffffffu, m, off));
        float e0 = __expf(v0 - m);
        float e1 = (lane + 32 < TWIN) ? __expf(v1 - m) : 0.0f;
        float s = e0 + e1;
        #pragma unroll
        for (int off = 16; off; off >>= 1)
            s += __shfl_xor_sync(0xffffffffu, s, off);
        float inv = 1.0f / s;
        S[row * S_STRIDE + lane] = e0 * inv;
        if (lane + 32 < TWIN) S[row * S_STRIDE + lane + 32] = e1 * inv;
    }
    __syncthreads();

    for (int t = tid; t < 13 * 16; t += 256) {
        int qg = t / 16, dp = t - qg * 16;
        int qi0 = qg * 4, d = dp * 2;
        float ax0 = 0, ay0 = 0, ax1 = 0, ay1 = 0,
              ax2 = 0, ay2 = 0, ax3 = 0, ay3 = 0;
        for (int ki = 0; ki < TWIN; ki++) {
            float2 vv = *(const float2*)&vs[ki * QS_STRIDE + d];
            float s0 = S[(qi0 + 0) * S_STRIDE + ki];
            float s1 = S[(qi0 + 1) * S_STRIDE + ki];
            float s2 = S[(qi0 + 2) * S_STRIDE + ki];
            float s3 = S[(qi0 + 3) * S_STRIDE + ki];
            ax0 = fmaf(s0, vv.x, ax0); ay0 = fmaf(s0, vv.y, ay0);
            ax1 = fmaf(s1, vv.x, ax1); ay1 = fmaf(s1, vv.y, ay1);
            ax2 = fmaf(s2, vv.x, ax2); ay2 = fmaf(s2, vv.y, ay2);
            ax3 = fmaf(s3, vv.x, ax3); ay3 = fmaf(s3, vv.y, ay3);
        }
        float axs[4] = {ax0, ax1, ax2, ax3};
        float ays[4] = {ay0, ay1, ay2, ay3};
        #pragma unroll
        for (int i = 0; i < 4; i++) {
            if (qi0 + i < TWIN) {
                float* dst = o + (size_t)tok[qi0 + i] * CDIM + head * HDIM + d;
                dst[0] = f2tf32f(axs[i]);
                dst[1] = f2tf32f(ays[i]);
            }
        }
    }
}

// ---------------- launch ----------------
extern "C" void kernel_launch(void* const* d_in, const int* in_sizes, int n_in,
                              void* d_out, int out_size)
{
    const float* x      = (const float*)d_in[0];
    const float* ln1_g  = (const float*)d_in[1];
    const float* ln1_b  = (const float*)d_in[2];
    const float* qkv_w  = (const float*)d_in[3];
    const float* qkv_b  = (const float*)d_in[4];
    const float* proj_w = (const float*)d_in[5];
    const float* proj_b = (const float*)d_in[6];
    const float* ln2_g  = (const float*)d_in[7];
    const float* ln2_b  = (const float*)d_in[8];
    const float* mlp_w1 = (const float*)d_in[9];
    const float* mlp_b1 = (const float*)d_in[10];
    const float* mlp_w2 = (const float*)d_in[11];
    const float* mlp_b2 = (const float*)d_in[12];
    float* out = (float*)d_out;

    float *p_qkv, *p_o, *p_x2, *p_h1, *p_wT;
    cudaGetSymbolAddress((void**)&p_qkv, g_qkv);
    cudaGetSymbolAddress((void**)&p_o,   g_o);
    cudaGetSymbolAddress((void**)&p_x2,  g_x2);
    cudaGetSymbolAddress((void**)&p_h1,  g_h1);
    cudaGetSymbolAddress((void**)&p_wT,  g_wT);
    float* wt_qkv  = p_wT;
    float* wt_proj = p_wT + W_QKV_N;
    float* wt_w1   = p_wT + W_QKV_N + W_PROJ_N;
    float* wt_w2   = p_wT + W_QKV_N + W_PROJ_N + W_W1_N;

    cudaFuncSetAttribute(tc_gemm<EPI_BIAS_RES>, cudaFuncAttributeMaxDynamicSharedMemorySize, SMEM_BYTES);
    cudaFuncSetAttribute(tc_gemm_lnA<EPI_BIAS>, cudaFuncAttributeMaxDynamicSharedMemorySize, LA_SMEM);
    cudaFuncSetAttribute(tc_gemm_lnA<EPI_GELU>, cudaFuncAttributeMaxDynamicSharedMemorySize, LA_SMEM);

    const int MT = NTOK / 128;  // 784

    // 0. weight rounding
    prep_kernel<<<(W_TOTAL + 255) / 256, 256>>>(qkv_w, proj_w, mlp_w1, mlp_w2, p_wT);
    // 1. qkv = LN1(x) @ qkv_w + qkv_b  (LN fused, A resident)
    tc_gemm_lnA<EPI_BIAS><<<dim3(3, MT), 128, LA_SMEM>>>(
        x, wt_qkv, qkv_b, ln1_g, ln1_b, p_qkv, 3 * CDIM);
    // 2. attention
    attn_kernel<<<NWIN * NHEAD, 256>>>(p_qkv, p_o);
    // 3. x2 = x + proj(o)
    tc_gemm<EPI_BIAS_RES><<<dim3(1, MT), 128, SMEM_BYTES>>>(
        p_o, wt_proj, proj_b, x, p_x2, CDIM, CDIM);
    // 4. h1 = gelu(LN2(x2) @ w1 + b1)  (LN fused, A resident)
    tc_gemm_lnA<EPI_GELU><<<dim3(4, MT), 128, LA_SMEM>>>(
        p_x2, wt_w1, mlp_b1, ln2_g, ln2_b, p_h1, HID);
    // 5. out = x2 + h1 @ w2 + b2
    tc_gemm<EPI_BIAS_RES><<<dim3(1, MT), 128, SMEM_BYTES>>>(
        p_h1, wt_w2, mlp_b2, p_x2, out, CDIM, HID);
}

// round 9
// speedup vs baseline: 1.8122x; 1.7241x over previous
#include <cuda_runtime.h>
#include <cuda_fp16.h>
#include <mma.h>
#include <math.h>
#include <stdint.h>

using namespace nvcuda;

// ---------------- problem constants ----------------
#define RESO 56
#define WS   7
#define CDIM 128
#define NHEAD 4
#define HDIM 32
#define HID  512
#define BATCH 32
#define NTOK (BATCH * RESO * RESO)      // 100352
#define NWIN (BATCH * 8 * 8)            // 2048 windows
#define TWIN 49

#define W_QKV_N 49152
#define W_PROJ_N 16384
#define W_W1_N 65536
#define W_W2_N 65536
#define W_TOTAL (W_QKV_N + W_PROJ_N + W_W1_N + W_W2_N)
#define W_BLOCKS ((W_TOTAL + 255) / 256)          // 769
#define LN_BLOCKS ((NTOK * 32) / 256)             // 12544

// ---------------- device scratch ----------------
__device__ __half g_lnh[(size_t)NTOK * CDIM];   // LN1 / LN2 output (half)
__device__ float  g_qkv[(size_t)NTOK * 3 * CDIM];
__device__ __half g_oh [(size_t)NTOK * CDIM];   // attention output (half)
__device__ float  g_x2 [(size_t)NTOK * CDIM];
__device__ __half g_h1h[(size_t)NTOK * HID];    // gelu(mlp1) (half)
__device__ __half g_wTh[W_TOTAL];               // half weights

__device__ __forceinline__ uint32_t smem_u32(const void* p) {
    uint32_t a;
    asm("{ .reg .u64 t; cvta.to.shared.u64 t, %1; cvt.u32.u64 %0, t; }" : "=r"(a) : "l"(p));
    return a;
}
__device__ __forceinline__ void cp_async16(uint32_t saddr, const void* gaddr) {
    asm volatile("cp.async.ca.shared.global [%0], [%1], 16;" :: "r"(saddr), "l"(gaddr));
}
#define CP_COMMIT() asm volatile("cp.async.commit_group;" ::: "memory")
#define CP_WAIT(n)  asm volatile("cp.async.wait_group %0;" :: "n"(n) : "memory")

__device__ __forceinline__ void store_half4(__half* dst, float a, float b, float c, float d) {
    __half2 h01 = __floats2half2_rn(a, b);
    __half2 h23 = __floats2half2_rn(c, d);
    uint2 u;
    u.x = *(uint32_t*)&h01;
    u.y = *(uint32_t*)&h23;
    *(uint2*)dst = u;
}

// ---------------- fused prep: weight->half + LN1->half ----------------
__global__ void prep_kernel(const float* __restrict__ w0, const float* __restrict__ w1,
                            const float* __restrict__ w2, const float* __restrict__ w3,
                            __half* __restrict__ WT,
                            const float* __restrict__ x, const float* __restrict__ g,
                            const float* __restrict__ b, __half* __restrict__ out)
{
    if (blockIdx.x < W_BLOCKS) {
        int idx = blockIdx.x * 256 + threadIdx.x;
        if (idx >= W_TOTAL) return;
        float v;
        if (idx < W_QKV_N)                          v = w0[idx];
        else if (idx < W_QKV_N + W_PROJ_N)          v = w1[idx - W_QKV_N];
        else if (idx < W_QKV_N + W_PROJ_N + W_W1_N) v = w2[idx - W_QKV_N - W_PROJ_N];
        else                                        v = w3[idx - W_QKV_N - W_PROJ_N - W_W1_N];
        WT[idx] = __float2half_rn(v);
        return;
    }
    int gwarp = ((blockIdx.x - W_BLOCKS) * 256 + threadIdx.x) >> 5;
    int lane  = threadIdx.x & 31;
    if (gwarp >= NTOK) return;
    float4 v = ((const float4*)(x + (size_t)gwarp * CDIM))[lane];
    float s  = v.x + v.y + v.z + v.w;
    float ss = v.x*v.x + v.y*v.y + v.z*v.z + v.w*v.w;
    #pragma unroll
    for (int off = 16; off; off >>= 1) {
        s  += __shfl_xor_sync(0xffffffffu, s,  off);
        ss += __shfl_xor_sync(0xffffffffu, ss, off);
    }
    float mean = s * (1.0f / CDIM);
    float var  = ss * (1.0f / CDIM) - mean * mean;
    float rstd = rsqrtf(var + 1e-5f);
    float4 gg = ((const float4*)g)[lane];
    float4 bb = ((const float4*)b)[lane];
    store_half4(out + (size_t)gwarp * CDIM + lane * 4,
                (v.x - mean) * rstd * gg.x + bb.x,
                (v.y - mean) * rstd * gg.y + bb.y,
                (v.z - mean) * rstd * gg.z + bb.z,
                (v.w - mean) * rstd * gg.w + bb.w);
}

// ---------------- fp16 WMMA GEMM: C = epi(A @ B + bias) -------------------
// CTA tile 128x128, 4 warps (2x2), warp tile 64x64 (4x4 of m16n16k16).
// K-chunks of 32 (2 ksteps), double-buffered cp.async. A,B half; acc fp32.
enum { EPI_BIAS = 0, EPI_BIAS_RES = 1, EPI_GELU = 2, EPI_RES_LN2 = 3 };

#define AH_STRIDE 40    // halves (80 B)
#define BH_STRIDE 136   // halves (272 B)
#define C_STRIDE  132   // floats (epilogue staging)
#define ABUFH (128 * AH_STRIDE * 2)     // 10240 B
#define BBUFH (32 * BH_STRIDE * 2)      // 8704 B
#define SMEM_BYTES (128 * C_STRIDE * 4) // 67584 B (epilogue dominates)

template <int EPI>
__global__ void __launch_bounds__(128, 2)
tc_gemm(const __half* __restrict__ A, const __half* __restrict__ B,
        const float* __restrict__ bias, const float* __restrict__ res,
        float* __restrict__ Cf, __half* __restrict__ Ch, int N, int K,
        const float* __restrict__ lng, const float* __restrict__ lnb,
        __half* __restrict__ C2)
{
    extern __shared__ char smem[];
    uint32_t sbase = smem_u32(smem);
    const int tid = threadIdx.x;
    const int wid = tid >> 5;
    const int warpM = wid & 1;
    const int warpN = wid >> 1;
    const int M0 = blockIdx.y * 128;
    const int N0 = blockIdx.x * 128;

    const __half* Abase = A + (size_t)M0 * K;
    const __half* Bbase = B + N0;
    const int nchunk = K >> 5;

    wmma::fragment<wmma::accumulator, 16, 16, 16, float> acc[4][4];
    #pragma unroll
    for (int i = 0; i < 4; i++)
        #pragma unroll
        for (int j = 0; j < 4; j++) wmma::fill_fragment(acc[i][j], 0.0f);

    auto load_chunk = [&](int c) {
        int buf = c & 1;
        uint32_t sa = sbase + buf * ABUFH;
        uint32_t sb = sbase + 2 * ABUFH + buf * BBUFH;
        int k0 = c << 5;
        #pragma unroll
        for (int q = 0; q < 4; q++) {       // A: 512 x 16B chunks
            int e = tid + q * 128;
            int row = e >> 2, c8 = (e & 3) * 8;
            cp_async16(sa + (row * AH_STRIDE + c8) * 2,
                       Abase + (size_t)row * K + k0 + c8);
        }
        #pragma unroll
        for (int q = 0; q < 4; q++) {       // B: 512 x 16B chunks
            int e = tid + q * 128;
            int row = e >> 4, c8 = (e & 15) * 8;
            cp_async16(sb + (row * BH_STRIDE + c8) * 2,
                       Bbase + (size_t)(k0 + row) * N + c8);
        }
    };

    load_chunk(0);
    CP_COMMIT();

    for (int c = 0; c < nchunk; c++) {
        if (c + 1 < nchunk) {
            load_chunk(c + 1);
            CP_COMMIT();
            CP_WAIT(1);
        } else {
            CP_WAIT(0);
        }
        __syncthreads();

        int buf = c & 1;
        const __half* As = (const __half*)(smem + buf * ABUFH);
        const __half* Bs = (const __half*)(smem + 2 * ABUFH + buf * BBUFH);
        #pragma unroll
        for (int ks = 0; ks < 2; ks++) {
            wmma::fragment<wmma::matrix_a, 16, 16, 16, __half, wmma::row_major> af[4];
            wmma::fragment<wmma::matrix_b, 16, 16, 16, __half, wmma::row_major> bf[4];
            #pragma unroll
            for (int i = 0; i < 4; i++)
                wmma::load_matrix_sync(af[i],
                    As + (warpM * 64 + i * 16) * AH_STRIDE + ks * 16, AH_STRIDE);
            #pragma unroll
            for (int j = 0; j < 4; j++)
                wmma::load_matrix_sync(bf[j],
                    Bs + (ks * 16) * BH_STRIDE + warpN * 64 + j * 16, BH_STRIDE);
            #pragma unroll
            for (int i = 0; i < 4; i++)
                #pragma unroll
                for (int j = 0; j < 4; j++)
                    wmma::mma_sync(acc[i][j], af[i], bf[j], acc[i][j]);
        }
        __syncthreads();
    }

    // stage accumulators in smem (fp32)
    float* Cs = (float*)smem;
    #pragma unroll
    for (int i = 0; i < 4; i++)
        #pragma unroll
        for (int j = 0; j < 4; j++)
            wmma::store_matrix_sync(
                Cs + (warpM * 64 + i * 16) * C_STRIDE + warpN * 64 + j * 16,
                acc[i][j], C_STRIDE, wmma::mem_row_major);
    __syncthreads();

    #pragma unroll
    for (int e0 = 0; e0 < 32; e0++) {
        int e = tid + e0 * 128;
        int row = e >> 5;
        int c4  = (e & 31) * 4;
        size_t roff = (size_t)(M0 + row) * N + N0 + c4;
        float v[4];
        #pragma unroll
        for (int q = 0; q < 4; q++) {
            float t = Cs[row * C_STRIDE + c4 + q] + __ldg(bias + N0 + c4 + q);
            if (EPI == EPI_BIAS_RES || EPI == EPI_RES_LN2) t += res[roff + q];
            if (EPI == EPI_GELU)
                t = 0.5f * t * (1.0f + erff(t * 0.70710678118654752f));
            v[q] = t;
        }
        if (EPI == EPI_GELU) {
            store_half4(Ch + roff, v[0], v[1], v[2], v[3]);
        } else {
            *(float4*)(Cf + roff) = *(float4*)v;
        }
        if (EPI == EPI_RES_LN2) {
            // N==128: this warp's 128 values are the whole token row.
            float s  = v[0] + v[1] + v[2] + v[3];
            float ss = v[0]*v[0] + v[1]*v[1] + v[2]*v[2] + v[3]*v[3];
            #pragma unroll
            for (int off = 16; off; off >>= 1) {
                s  += __shfl_xor_sync(0xffffffffu, s,  off);
                ss += __shfl_xor_sync(0xffffffffu, ss, off);
            }
            float mean = s * (1.0f / CDIM);
            float var  = ss * (1.0f / CDIM) - mean * mean;
            float rstd = rsqrtf(var + 1e-5f);
            store_half4(C2 + roff,
                        (v[0] - mean) * rstd * __ldg(lng + c4 + 0) + __ldg(lnb + c4 + 0),
                        (v[1] - mean) * rstd * __ldg(lng + c4 + 1) + __ldg(lnb + c4 + 1),
                        (v[2] - mean) * rstd * __ldg(lng + c4 + 2) + __ldg(lnb + c4 + 2),
                        (v[3] - mean) * rstd * __ldg(lng + c4 + 3) + __ldg(lnb + c4 + 3));
        }
    }
}

// ---------------- windowed attention (R6 proven; half output) --------------
#define QS_STRIDE 36
#define S_STRIDE  50

__global__ __launch_bounds__(256)
void attn_kernel(const float* __restrict__ qkv, __half* __restrict__ o)
{
    int blk  = blockIdx.x;
    int head = blk & 3;
    int w    = blk >> 2;
    int bimg = w >> 6;
    int win  = w & 63;
    int wr   = win >> 3, wc = win & 7;

    __shared__ int tok[TWIN];
    __shared__ __align__(16) float qs[52 * QS_STRIDE];
    __shared__ __align__(16) float ks[50 * QS_STRIDE];
    __shared__ __align__(16) float vs[49 * QS_STRIDE];
    __shared__ __align__(16) float S[52 * S_STRIDE];

    int tid = threadIdx.x;
    if (tid < TWIN) {
        int r = tid / WS, c = tid - r * WS;
        tok[tid] = bimg * (RESO * RESO) + (wr * WS + r) * RESO + (wc * WS + c);
    }
    if (tid < 3 * QS_STRIDE) qs[49 * QS_STRIDE + tid] = 0.0f;
    if (tid >= 128 && tid < 128 + QS_STRIDE) ks[49 * QS_STRIDE + (tid - 128)] = 0.0f;
    __syncthreads();

    for (int idx = tid; idx < TWIN * HDIM * 3; idx += 256) {
        int which = idx / (TWIN * HDIM);
        int rem   = idx - which * (TWIN * HDIM);
        int t = rem >> 5, d = rem & 31;
        float val = qkv[(size_t)tok[t] * (3 * CDIM) + which * CDIM + head * HDIM + d];
        float* dst = (which == 0) ? qs : (which == 1) ? ks : vs;
        dst[t * QS_STRIDE + d] = val;
    }
    __syncthreads();

    const float scale = 0.17677669529663687f;
    for (int t = tid; t < 13 * 25; t += 256) {
        int qg = t / 25, kg = t - qg * 25;
        int qi0 = qg * 4, ki0 = kg * 2;
        float a[4][2];
        #pragma unroll
        for (int i = 0; i < 4; i++) { a[i][0] = 0.0f; a[i][1] = 0.0f; }
        #pragma unroll
        for (int dq = 0; dq < 8; dq++) {
            float4 k0 = *(const float4*)&ks[ki0 * QS_STRIDE + 4 * dq];
            float4 k1 = *(const float4*)&ks[(ki0 + 1) * QS_STRIDE + 4 * dq];
            #pragma unroll
            for (int i = 0; i < 4; i++) {
                float4 q = *(const float4*)&qs[(qi0 + i) * QS_STRIDE + 4 * dq];
                a[i][0] = fmaf(q.x, k0.x, fmaf(q.y, k0.y, fmaf(q.z, k0.z, fmaf(q.w, k0.w, a[i][0]))));
                a[i][1] = fmaf(q.x, k1.x, fmaf(q.y, k1.y, fmaf(q.z, k1.z, fmaf(q.w, k1.w, a[i][1]))));
            }
        }
        #pragma unroll
        for (int i = 0; i < 4; i++)
            if (qi0 + i < TWIN)
                #pragma unroll
                for (int j = 0; j < 2; j++)
                    if (ki0 + j < TWIN)
                        S[(qi0 + i) * S_STRIDE + ki0 + j] = a[i][j] * scale;
    }
    __syncthreads();

    int warp = tid >> 5, lane = tid & 31;
    for (int row = warp; row < TWIN; row += 8) {
        float v0 = S[row * S_STRIDE + lane];
        float v1 = (lane + 32 < TWIN) ? S[row * S_STRIDE + lane + 32] : -3.4e38f;
        float m = fmaxf(v0, v1);
        #pragma unroll
        for (int off = 16; off; off >>= 1)
            m = fmaxf(m, __shfl_xor_sync(0xffffffffu, m, off));
        float e0 = __expf(v0 - m);
        float e1 = (lane + 32 < TWIN) ? __expf(v1 - m) : 0.0f;
        float s = e0 + e1;
        #pragma unroll
        for (int off = 16; off; off >>= 1)
            s += __shfl_xor_sync(0xffffffffu, s, off);
        float inv = 1.0f / s;
        S[row * S_STRIDE + lane] = e0 * inv;
        if (lane + 32 < TWIN) S[row * S_STRIDE + lane + 32] = e1 * inv;
    }
    __syncthreads();

    for (int t = tid; t < 13 * 16; t += 256) {
        int qg = t / 16, dp = t - qg * 16;
        int qi0 = qg * 4, d = dp * 2;
        float ax0 = 0, ay0 = 0, ax1 = 0, ay1 = 0,
              ax2 = 0, ay2 = 0, ax3 = 0, ay3 = 0;
        for (int ki = 0; ki < TWIN; ki++) {
            float2 vv = *(const float2*)&vs[ki * QS_STRIDE + d];
            float s0 = S[(qi0 + 0) * S_STRIDE + ki];
            float s1 = S[(qi0 + 1) * S_STRIDE + ki];
            float s2 = S[(qi0 + 2) * S_STRIDE + ki];
            float s3 = S[(qi0 + 3) * S_STRIDE + ki];
            ax0 = fmaf(s0, vv.x, ax0); ay0 = fmaf(s0, vv.y, ay0);
            ax1 = fmaf(s1, vv.x, ax1); ay1 = fmaf(s1, vv.y, ay1);
            ax2 = fmaf(s2, vv.x, ax2); ay2 = fmaf(s2, vv.y, ay2);
            ax3 = fmaf(s3, vv.x, ax3); ay3 = fmaf(s3, vv.y, ay3);
        }
        float axs[4] = {ax0, ax1, ax2, ax3};
        float ays[4] = {ay0, ay1, ay2, ay3};
        #pragma unroll
        for (int i = 0; i < 4; i++) {
            if (qi0 + i < TWIN) {
                __half2 p = __floats2half2_rn(axs[i], ays[i]);
                *(__half2*)(o + (size_t)tok[qi0 + i] * CDIM + head * HDIM + d) = p;
            }
        }
    }
}

// ---------------- launch ----------------
extern "C" void kernel_launch(void* const* d_in, const int* in_sizes, int n_in,
                              void* d_out, int out_size)
{
    const float* x      = (const float*)d_in[0];
    const float* ln1_g  = (const float*)d_in[1];
    const float* ln1_b  = (const float*)d_in[2];
    const float* qkv_w  = (const float*)d_in[3];
    const float* qkv_b  = (const float*)d_in[4];
    const float* proj_w = (const float*)d_in[5];
    const float* proj_b = (const float*)d_in[6];
    const float* ln2_g  = (const float*)d_in[7];
    const float* ln2_b  = (const float*)d_in[8];
    const float* mlp_w1 = (const float*)d_in[9];
    const float* mlp_b1 = (const float*)d_in[10];
    const float* mlp_w2 = (const float*)d_in[11];
    const float* mlp_b2 = (const float*)d_in[12];
    float* out = (float*)d_out;

    __half *p_lnh, *p_oh, *p_h1h, *p_wTh;
    float *p_qkv, *p_x2;
    cudaGetSymbolAddress((void**)&p_lnh, g_lnh);
    cudaGetSymbolAddress((void**)&p_qkv, g_qkv);
    cudaGetSymbolAddress((void**)&p_oh,  g_oh);
    cudaGetSymbolAddress((void**)&p_x2,  g_x2);
    cudaGetSymbolAddress((void**)&p_h1h, g_h1h);
    cudaGetSymbolAddress((void**)&p_wTh, g_wTh);
    __half* wt_qkv  = p_wTh;
    __half* wt_proj = p_wTh + W_QKV_N;
    __half* wt_w1   = p_wTh + W_QKV_N + W_PROJ_N;
    __half* wt_w2   = p_wTh + W_QKV_N + W_PROJ_N + W_W1_N;

    cudaFuncSetAttribute(tc_gemm<EPI_BIAS>,     cudaFuncAttributeMaxDynamicSharedMemorySize, SMEM_BYTES);
    cudaFuncSetAttribute(tc_gemm<EPI_BIAS_RES>, cudaFuncAttributeMaxDynamicSharedMemorySize, SMEM_BYTES);
    cudaFuncSetAttribute(tc_gemm<EPI_GELU>,     cudaFuncAttributeMaxDynamicSharedMemorySize, SMEM_BYTES);
    cudaFuncSetAttribute(tc_gemm<EPI_RES_LN2>,  cudaFuncAttributeMaxDynamicSharedMemorySize, SMEM_BYTES);

    const int MT = NTOK / 128;  // 784

    // 0. fused prep: weight->half + LN1->half
    prep_kernel<<<W_BLOCKS + LN_BLOCKS, 256>>>(qkv_w, proj_w, mlp_w1, mlp_w2, p_wTh,
                                               x, ln1_g, ln1_b, p_lnh);
    // 1. QKV = ln1 @ qkv_w + qkv_b  (fp32 out for attention)
    tc_gemm<EPI_BIAS><<<dim3(3, MT), 128, SMEM_BYTES>>>(
        p_lnh, wt_qkv, qkv_b, nullptr, p_qkv, nullptr, 3 * CDIM, CDIM,
        nullptr, nullptr, nullptr);
    // 2. attention -> half
    attn_kernel<<<NWIN * NHEAD, 256>>>(p_qkv, p_oh);
    // 3. x2 = x + proj(o)  (fp32) ; fused LN2 -> half
    tc_gemm<EPI_RES_LN2><<<dim3(1, MT), 128, SMEM_BYTES>>>(
        p_oh, wt_proj, proj_b, x, p_x2, nullptr, CDIM, CDIM,
        ln2_g, ln2_b, p_lnh);
    // 4. h1 = gelu(ln2 @ w1 + b1) -> half
    tc_gemm<EPI_GELU><<<dim3(4, MT), 128, SMEM_BYTES>>>(
        p_lnh, wt_w1, mlp_b1, nullptr, nullptr, p_h1h, HID, CDIM,
        nullptr, nullptr, nullptr);
    // 5. out = x2 + h1 @ w2 + b2  (fp32)
    tc_gemm<EPI_BIAS_RES><<<dim3(1, MT), 128, SMEM_BYTES>>>(
        p_h1h, wt_w2, mlp_b2, p_x2, out, nullptr, CDIM, HID,
        nullptr, nullptr, nullptr);
}

// round 10
// speedup vs baseline: 2.2000x; 1.2140x over previous
#include <cuda_runtime.h>
#include <cuda_fp16.h>
#include <mma.h>
#include <math.h>
#include <stdint.h>

using namespace nvcuda;

// ---------------- problem constants ----------------
#define RESO 56
#define WS   7
#define CDIM 128
#define NHEAD 4
#define HDIM 32
#define HID  512
#define BATCH 32
#define NTOK (BATCH * RESO * RESO)      // 100352
#define NWIN (BATCH * 8 * 8)            // 2048 windows
#define TWIN 49

#define W_QKV_N 49152
#define W_PROJ_N 16384
#define W_W1_N 65536
#define W_W2_N 65536
#define W_TOTAL (W_QKV_N + W_PROJ_N + W_W1_N + W_W2_N)
#define W_BLOCKS ((W_TOTAL + 255) / 256)          // 769
#define LN_BLOCKS ((NTOK * 32) / 256)             // 12544

// ---------------- device scratch ----------------
__device__ __half g_lnh[(size_t)NTOK * CDIM];   // LN1 / LN2 output (half)
__device__ __half g_qkvh[(size_t)NTOK * 3 * CDIM];  // qkv (half)
__device__ __half g_oh [(size_t)NTOK * CDIM];   // attention output (half)
__device__ float  g_x2 [(size_t)NTOK * CDIM];
__device__ __half g_h1h[(size_t)NTOK * HID];    // gelu(mlp1) (half)
__device__ __half g_wTh[W_TOTAL];               // half weights

__device__ __forceinline__ uint32_t smem_u32(const void* p) {
    uint32_t a;
    asm("{ .reg .u64 t; cvta.to.shared.u64 t, %1; cvt.u32.u64 %0, t; }" : "=r"(a) : "l"(p));
    return a;
}
__device__ __forceinline__ void cp_async16(uint32_t saddr, const void* gaddr) {
    asm volatile("cp.async.ca.shared.global [%0], [%1], 16;" :: "r"(saddr), "l"(gaddr));
}
#define CP_COMMIT() asm volatile("cp.async.commit_group;" ::: "memory")
#define CP_WAIT(n)  asm volatile("cp.async.wait_group %0;" :: "n"(n) : "memory")

__device__ __forceinline__ void store_half4(__half* dst, float a, float b, float c, float d) {
    __half2 h01 = __floats2half2_rn(a, b);
    __half2 h23 = __floats2half2_rn(c, d);
    uint2 u;
    u.x = *(uint32_t*)&h01;
    u.y = *(uint32_t*)&h23;
    *(uint2*)dst = u;
}

// ---------------- fused prep: weight->half + LN1->half ----------------
__global__ void prep_kernel(const float* __restrict__ w0, const float* __restrict__ w1,
                            const float* __restrict__ w2, const float* __restrict__ w3,
                            __half* __restrict__ WT,
                            const float* __restrict__ x, const float* __restrict__ g,
                            const float* __restrict__ b, __half* __restrict__ out)
{
    if (blockIdx.x < W_BLOCKS) {
        int idx = blockIdx.x * 256 + threadIdx.x;
        if (idx >= W_TOTAL) return;
        float v;
        if (idx < W_QKV_N)                          v = w0[idx];
        else if (idx < W_QKV_N + W_PROJ_N)          v = w1[idx - W_QKV_N];
        else if (idx < W_QKV_N + W_PROJ_N + W_W1_N) v = w2[idx - W_QKV_N - W_PROJ_N];
        else                                        v = w3[idx - W_QKV_N - W_PROJ_N - W_W1_N];
        WT[idx] = __float2half_rn(v);
        return;
    }
    int gwarp = ((blockIdx.x - W_BLOCKS) * 256 + threadIdx.x) >> 5;
    int lane  = threadIdx.x & 31;
    if (gwarp >= NTOK) return;
    float4 v = ((const float4*)(x + (size_t)gwarp * CDIM))[lane];
    float s  = v.x + v.y + v.z + v.w;
    float ss = v.x*v.x + v.y*v.y + v.z*v.z + v.w*v.w;
    #pragma unroll
    for (int off = 16; off; off >>= 1) {
        s  += __shfl_xor_sync(0xffffffffu, s,  off);
        ss += __shfl_xor_sync(0xffffffffu, ss, off);
    }
    float mean = s * (1.0f / CDIM);
    float var  = ss * (1.0f / CDIM) - mean * mean;
    float rstd = rsqrtf(var + 1e-5f);
    float4 gg = ((const float4*)g)[lane];
    float4 bb = ((const float4*)b)[lane];
    store_half4(out + (size_t)gwarp * CDIM + lane * 4,
                (v.x - mean) * rstd * gg.x + bb.x,
                (v.y - mean) * rstd * gg.y + bb.y,
                (v.z - mean) * rstd * gg.z + bb.z,
                (v.w - mean) * rstd * gg.w + bb.w);
}

// ---------------- fp16 WMMA GEMM: C = epi(A @ B + bias) -------------------
// CTA tile 128x128, 4 warps (2x2), warp tile 64x64 (4x4 of m16n16k16).
// K-chunks of 32 (2 ksteps), double-buffered cp.async. A,B half; acc fp32.
// EPI_BIAS and EPI_GELU store half (Ch); others store fp32 (Cf).
enum { EPI_BIAS = 0, EPI_BIAS_RES = 1, EPI_GELU = 2, EPI_RES_LN2 = 3 };

#define AH_STRIDE 40    // halves (80 B)
#define BH_STRIDE 136   // halves (272 B)
#define C_STRIDE  132   // floats (epilogue staging)
#define ABUFH (128 * AH_STRIDE * 2)     // 10240 B
#define BBUFH (32 * BH_STRIDE * 2)      // 8704 B
#define SMEM_BYTES (128 * C_STRIDE * 4) // 67584 B (epilogue dominates)

template <int EPI>
__global__ void __launch_bounds__(128, 2)
tc_gemm(const __half* __restrict__ A, const __half* __restrict__ B,
        const float* __restrict__ bias, const float* __restrict__ res,
        float* __restrict__ Cf, __half* __restrict__ Ch, int N, int K,
        const float* __restrict__ lng, const float* __restrict__ lnb,
        __half* __restrict__ C2)
{
    extern __shared__ char smem[];
    uint32_t sbase = smem_u32(smem);
    const int tid = threadIdx.x;
    const int wid = tid >> 5;
    const int warpM = wid & 1;
    const int warpN = wid >> 1;
    const int M0 = blockIdx.y * 128;
    const int N0 = blockIdx.x * 128;

    const __half* Abase = A + (size_t)M0 * K;
    const __half* Bbase = B + N0;
    const int nchunk = K >> 5;

    wmma::fragment<wmma::accumulator, 16, 16, 16, float> acc[4][4];
    #pragma unroll
    for (int i = 0; i < 4; i++)
        #pragma unroll
        for (int j = 0; j < 4; j++) wmma::fill_fragment(acc[i][j], 0.0f);

    auto load_chunk = [&](int c) {
        int buf = c & 1;
        uint32_t sa = sbase + buf * ABUFH;
        uint32_t sb = sbase + 2 * ABUFH + buf * BBUFH;
        int k0 = c << 5;
        #pragma unroll
        for (int q = 0; q < 4; q++) {       // A: 512 x 16B chunks
            int e = tid + q * 128;
            int row = e >> 2, c8 = (e & 3) * 8;
            cp_async16(sa + (row * AH_STRIDE + c8) * 2,
                       Abase + (size_t)row * K + k0 + c8);
        }
        #pragma unroll
        for (int q = 0; q < 4; q++) {       // B: 512 x 16B chunks
            int e = tid + q * 128;
            int row = e >> 4, c8 = (e & 15) * 8;
            cp_async16(sb + (row * BH_STRIDE + c8) * 2,
                       Bbase + (size_t)(k0 + row) * N + c8);
        }
    };

    load_chunk(0);
    CP_COMMIT();

    for (int c = 0; c < nchunk; c++) {
        if (c + 1 < nchunk) {
            load_chunk(c + 1);
            CP_COMMIT();
            CP_WAIT(1);
        } else {
            CP_WAIT(0);
        }
        __syncthreads();

        int buf = c & 1;
        const __half* As = (const __half*)(smem + buf * ABUFH);
        const __half* Bs = (const __half*)(smem + 2 * ABUFH + buf * BBUFH);
        #pragma unroll
        for (int ks = 0; ks < 2; ks++) {
            wmma::fragment<wmma::matrix_a, 16, 16, 16, __half, wmma::row_major> af[4];
            wmma::fragment<wmma::matrix_b, 16, 16, 16, __half, wmma::row_major> bf[4];
            #pragma unroll
            for (int i = 0; i < 4; i++)
                wmma::load_matrix_sync(af[i],
                    As + (warpM * 64 + i * 16) * AH_STRIDE + ks * 16, AH_STRIDE);
            #pragma unroll
            for (int j = 0; j < 4; j++)
                wmma::load_matrix_sync(bf[j],
                    Bs + (ks * 16) * BH_STRIDE + warpN * 64 + j * 16, BH_STRIDE);
            #pragma unroll
            for (int i = 0; i < 4; i++)
                #pragma unroll
                for (int j = 0; j < 4; j++)
                    wmma::mma_sync(acc[i][j], af[i], bf[j], acc[i][j]);
        }
        __syncthreads();
    }

    // stage accumulators in smem (fp32)
    float* Cs = (float*)smem;
    #pragma unroll
    for (int i = 0; i < 4; i++)
        #pragma unroll
        for (int j = 0; j < 4; j++)
            wmma::store_matrix_sync(
                Cs + (warpM * 64 + i * 16) * C_STRIDE + warpN * 64 + j * 16,
                acc[i][j], C_STRIDE, wmma::mem_row_major);
    __syncthreads();

    #pragma unroll
    for (int e0 = 0; e0 < 32; e0++) {
        int e = tid + e0 * 128;
        int row = e >> 5;
        int c4  = (e & 31) * 4;
        size_t roff = (size_t)(M0 + row) * N + N0 + c4;
        float v[4];
        #pragma unroll
        for (int q = 0; q < 4; q++) {
            float t = Cs[row * C_STRIDE + c4 + q] + __ldg(bias + N0 + c4 + q);
            if (EPI == EPI_BIAS_RES || EPI == EPI_RES_LN2) t += res[roff + q];
            if (EPI == EPI_GELU)
                t = 0.5f * t * (1.0f + erff(t * 0.70710678118654752f));
            v[q] = t;
        }
        if (EPI == EPI_GELU || EPI == EPI_BIAS) {
            store_half4(Ch + roff, v[0], v[1], v[2], v[3]);
        } else {
            *(float4*)(Cf + roff) = *(float4*)v;
        }
        if (EPI == EPI_RES_LN2) {
            // N==128: this warp's 128 values are the whole token row.
            float s  = v[0] + v[1] + v[2] + v[3];
            float ss = v[0]*v[0] + v[1]*v[1] + v[2]*v[2] + v[3]*v[3];
            #pragma unroll
            for (int off = 16; off; off >>= 1) {
                s  += __shfl_xor_sync(0xffffffffu, s,  off);
                ss += __shfl_xor_sync(0xffffffffu, ss, off);
            }
            float mean = s * (1.0f / CDIM);
            float var  = ss * (1.0f / CDIM) - mean * mean;
            float rstd = rsqrtf(var + 1e-5f);
            store_half4(C2 + roff,
                        (v[0] - mean) * rstd * __ldg(lng + c4 + 0) + __ldg(lnb + c4 + 0),
                        (v[1] - mean) * rstd * __ldg(lng + c4 + 1) + __ldg(lnb + c4 + 1),
                        (v[2] - mean) * rstd * __ldg(lng + c4 + 2) + __ldg(lnb + c4 + 2),
                        (v[3] - mean) * rstd * __ldg(lng + c4 + 3) + __ldg(lnb + c4 + 3));
        }
    }
}

// ---------------- windowed attention (half qkv in, half out) --------------
#define QS_STRIDE 36
#define S_STRIDE  50

__global__ __launch_bounds__(256)
void attn_kernel(const __half* __restrict__ qkv, __half* __restrict__ o)
{
    int blk  = blockIdx.x;
    int head = blk & 3;
    int w    = blk >> 2;
    int bimg = w >> 6;
    int win  = w & 63;
    int wr   = win >> 3, wc = win & 7;

    __shared__ int tok[TWIN];
    __shared__ __align__(16) float qs[52 * QS_STRIDE];
    __shared__ __align__(16) float ks[50 * QS_STRIDE];
    __shared__ __align__(16) float vs[49 * QS_STRIDE];
    __shared__ __align__(16) float S[52 * S_STRIDE];

    int tid = threadIdx.x;
    if (tid < TWIN) {
        int r = tid / WS, c = tid - r * WS;
        tok[tid] = bimg * (RESO * RESO) + (wr * WS + r) * RESO + (wc * WS + c);
    }
    if (tid < 3 * QS_STRIDE) qs[49 * QS_STRIDE + tid] = 0.0f;
    if (tid >= 128 && tid < 128 + QS_STRIDE) ks[49 * QS_STRIDE + (tid - 128)] = 0.0f;
    __syncthreads();

    // gather q,k,v (half2 loads -> float smem): 49*16*3 = 2352 half2 elements
    for (int idx = tid; idx < TWIN * 16 * 3; idx += 256) {
        int which = idx / (TWIN * 16);
        int rem   = idx - which * (TWIN * 16);
        int t = rem >> 4, dp = rem & 15;
        __half2 hv = *(const __half2*)(qkv + (size_t)tok[t] * (3 * CDIM)
                                       + which * CDIM + head * HDIM + dp * 2);
        float2 f = __half22float2(hv);
        float* dst = (which == 0) ? qs : (which == 1) ? ks : vs;
        dst[t * QS_STRIDE + dp * 2]     = f.x;
        dst[t * QS_STRIDE + dp * 2 + 1] = f.y;
    }
    __syncthreads();

    const float scale = 0.17677669529663687f;
    for (int t = tid; t < 13 * 25; t += 256) {
        int qg = t / 25, kg = t - qg * 25;
        int qi0 = qg * 4, ki0 = kg * 2;
        float a[4][2];
        #pragma unroll
        for (int i = 0; i < 4; i++) { a[i][0] = 0.0f; a[i][1] = 0.0f; }
        #pragma unroll
        for (int dq = 0; dq < 8; dq++) {
            float4 k0 = *(const float4*)&ks[ki0 * QS_STRIDE + 4 * dq];
            float4 k1 = *(const float4*)&ks[(ki0 + 1) * QS_STRIDE + 4 * dq];
            #pragma unroll
            for (int i = 0; i < 4; i++) {
                float4 q = *(const float4*)&qs[(qi0 + i) * QS_STRIDE + 4 * dq];
                a[i][0] = fmaf(q.x, k0.x, fmaf(q.y, k0.y, fmaf(q.z, k0.z, fmaf(q.w, k0.w, a[i][0]))));
                a[i][1] = fmaf(q.x, k1.x, fmaf(q.y, k1.y, fmaf(q.z, k1.z, fmaf(q.w, k1.w, a[i][1]))));
            }
        }
        #pragma unroll
        for (int i = 0; i < 4; i++)
            if (qi0 + i < TWIN)
                #pragma unroll
                for (int j = 0; j < 2; j++)
                    if (ki0 + j < TWIN)
                        S[(qi0 + i) * S_STRIDE + ki0 + j] = a[i][j] * scale;
    }
    __syncthreads();

    int warp = tid >> 5, lane = tid & 31;
    for (int row = warp; row < TWIN; row += 8) {
        float v0 = S[row * S_STRIDE + lane];
        float v1 = (lane + 32 < TWIN) ? S[row * S_STRIDE + lane + 32] : -3.4e38f;
        float m = fmaxf(v0, v1);
        #pragma unroll
        for (int off = 16; off; off >>= 1)
            m = fmaxf(m, __shfl_xor_sync(0xffffffffu, m, off));
        float e0 = __expf(v0 - m);
        float e1 = (lane + 32 < TWIN) ? __expf(v1 - m) : 0.0f;
        float s = e0 + e1;
        #pragma unroll
        for (int off = 16; off; off >>= 1)
            s += __shfl_xor_sync(0xffffffffu, s, off);
        float inv = 1.0f / s;
        S[row * S_STRIDE + lane] = e0 * inv;
        if (lane + 32 < TWIN) S[row * S_STRIDE + lane + 32] = e1 * inv;
    }
    __syncthreads();

    for (int t = tid; t < 13 * 16; t += 256) {
        int qg = t / 16, dp = t - qg * 16;
        int qi0 = qg * 4, d = dp * 2;
        float ax0 = 0, ay0 = 0, ax1 = 0, ay1 = 0,
              ax2 = 0, ay2 = 0, ax3 = 0, ay3 = 0;
        for (int ki = 0; ki < TWIN; ki++) {
            float2 vv = *(const float2*)&vs[ki * QS_STRIDE + d];
            float s0 = S[(qi0 + 0) * S_STRIDE + ki];
            float s1 = S[(qi0 + 1) * S_STRIDE + ki];
            float s2 = S[(qi0 + 2) * S_STRIDE + ki];
            float s3 = S[(qi0 + 3) * S_STRIDE + ki];
            ax0 = fmaf(s0, vv.x, ax0); ay0 = fmaf(s0, vv.y, ay0);
            ax1 = fmaf(s1, vv.x, ax1); ay1 = fmaf(s1, vv.y, ay1);
            ax2 = fmaf(s2, vv.x, ax2); ay2 = fmaf(s2, vv.y, ay2);
            ax3 = fmaf(s3, vv.x, ax3); ay3 = fmaf(s3, vv.y, ay3);
        }
        float axs[4] = {ax0, ax1, ax2, ax3};
        float ays[4] = {ay0, ay1, ay2, ay3};
        #pragma unroll
        for (int i = 0; i < 4; i++) {
            if (qi0 + i < TWIN) {
                __half2 p = __floats2half2_rn(axs[i], ays[i]);
                *(__half2*)(o + (size_t)tok[qi0 + i] * CDIM + head * HDIM + d) = p;
            }
        }
    }
}

// ---------------- launch ----------------
extern "C" void kernel_launch(void* const* d_in, const int* in_sizes, int n_in,
                              void* d_out, int out_size)
{
    const float* x      = (const float*)d_in[0];
    const float* ln1_g  = (const float*)d_in[1];
    const float* ln1_b  = (const float*)d_in[2];
    const float* qkv_w  = (const float*)d_in[3];
    const float* qkv_b  = (const float*)d_in[4];
    const float* proj_w = (const float*)d_in[5];
    const float* proj_b = (const float*)d_in[6];
    const float* ln2_g  = (const float*)d_in[7];
    const float* ln2_b  = (const float*)d_in[8];
    const float* mlp_w1 = (const float*)d_in[9];
    const float* mlp_b1 = (const float*)d_in[10];
    const float* mlp_w2 = (const float*)d_in[11];
    const float* mlp_b2 = (const float*)d_in[12];
    float* out = (float*)d_out;

    __half *p_lnh, *p_qkvh, *p_oh, *p_h1h, *p_wTh;
    float *p_x2;
    cudaGetSymbolAddress((void**)&p_lnh,  g_lnh);
    cudaGetSymbolAddress((void**)&p_qkvh, g_qkvh);
    cudaGetSymbolAddress((void**)&p_oh,   g_oh);
    cudaGetSymbolAddress((void**)&p_x2,   g_x2);
    cudaGetSymbolAddress((void**)&p_h1h,  g_h1h);
    cudaGetSymbolAddress((void**)&p_wTh,  g_wTh);
    __half* wt_qkv  = p_wTh;
    __half* wt_proj = p_wTh + W_QKV_N;
    __half* wt_w1   = p_wTh + W_QKV_N + W_PROJ_N;
    __half* wt_w2   = p_wTh + W_QKV_N + W_PROJ_N + W_W1_N;

    cudaFuncSetAttribute(tc_gemm<EPI_BIAS>,     cudaFuncAttributeMaxDynamicSharedMemorySize, SMEM_BYTES);
    cudaFuncSetAttribute(tc_gemm<EPI_BIAS_RES>, cudaFuncAttributeMaxDynamicSharedMemorySize, SMEM_BYTES);
    cudaFuncSetAttribute(tc_gemm<EPI_GELU>,     cudaFuncAttributeMaxDynamicSharedMemorySize, SMEM_BYTES);
    cudaFuncSetAttribute(tc_gemm<EPI_RES_LN2>,  cudaFuncAttributeMaxDynamicSharedMemorySize, SMEM_BYTES);

    const int MT = NTOK / 128;  // 784

    // 0. fused prep: weight->half + LN1->half
    prep_kernel<<<W_BLOCKS + LN_BLOCKS, 256>>>(qkv_w, proj_w, mlp_w1, mlp_w2, p_wTh,
                                               x, ln1_g, ln1_b, p_lnh);
    // 1. QKV = ln1 @ qkv_w + qkv_b  -> half
    tc_gemm<EPI_BIAS><<<dim3(3, MT), 128, SMEM_BYTES>>>(
        p_lnh, wt_qkv, qkv_b, nullptr, nullptr, p_qkvh, 3 * CDIM, CDIM,
        nullptr, nullptr, nullptr);
    // 2. attention (half in, half out)
    attn_kernel<<<NWIN * NHEAD, 256>>>(p_qkvh, p_oh);
    // 3. x2 = x + proj(o)  (fp32) ; fused LN2 -> half
    tc_gemm<EPI_RES_LN2><<<dim3(1, MT), 128, SMEM_BYTES>>>(
        p_oh, wt_proj, proj_b, x, p_x2, nullptr, CDIM, CDIM,
        ln2_g, ln2_b, p_lnh);
    // 4. h1 = gelu(ln2 @ w1 + b1) -> half
    tc_gemm<EPI_GELU><<<dim3(4, MT), 128, SMEM_BYTES>>>(
        p_lnh, wt_w1, mlp_b1, nullptr, nullptr, p_h1h, HID, CDIM,
        nullptr, nullptr, nullptr);
    // 5. out = x2 + h1 @ w2 + b2  (fp32)
    tc_gemm<EPI_BIAS_RES><<<dim3(1, MT), 128, SMEM_BYTES>>>(
        p_h1h, wt_w2, mlp_b2, p_x2, out, nullptr, CDIM, HID,
        nullptr, nullptr, nullptr);
}

// round 11
// speedup vs baseline: 2.3813x; 1.0824x over previous
#include <cuda_runtime.h>
#include <cuda_fp16.h>
#include <mma.h>
#include <math.h>
#include <stdint.h>

using namespace nvcuda;

// ---------------- problem constants ----------------
#define RESO 56
#define WS   7
#define CDIM 128
#define NHEAD 4
#define HDIM 32
#define HID  512
#define BATCH 32
#define NTOK (BATCH * RESO * RESO)      // 100352
#define NWIN (BATCH * 8 * 8)            // 2048 windows
#define TWIN 49

#define W_QKV_N 49152
#define W_PROJ_N 16384
#define W_W1_N 65536
#define W_W2_N 65536
#define W_TOTAL (W_QKV_N + W_PROJ_N + W_W1_N + W_W2_N)
#define W_BLOCKS ((W_TOTAL + 255) / 256)          // 769
#define LN_BLOCKS ((NTOK * 32) / 256)             // 12544

// ---------------- device scratch ----------------
__device__ __half g_lnh[(size_t)NTOK * CDIM];
__device__ __half g_qkvh[(size_t)NTOK * 3 * CDIM];
__device__ __half g_oh [(size_t)NTOK * CDIM];
__device__ float  g_x2 [(size_t)NTOK * CDIM];
__device__ __half g_h1h[(size_t)NTOK * HID];
__device__ __half g_wTh[W_TOTAL];

__device__ __forceinline__ uint32_t smem_u32(const void* p) {
    uint32_t a;
    asm("{ .reg .u64 t; cvta.to.shared.u64 t, %1; cvt.u32.u64 %0, t; }" : "=r"(a) : "l"(p));
    return a;
}
__device__ __forceinline__ void cp_async16(uint32_t saddr, const void* gaddr) {
    asm volatile("cp.async.ca.shared.global [%0], [%1], 16;" :: "r"(saddr), "l"(gaddr));
}
#define CP_COMMIT() asm volatile("cp.async.commit_group;" ::: "memory")
#define CP_WAIT(n)  asm volatile("cp.async.wait_group %0;" :: "n"(n) : "memory")

__device__ __forceinline__ void store_half4(__half* dst, float a, float b, float c, float d) {
    __half2 h01 = __floats2half2_rn(a, b);
    __half2 h23 = __floats2half2_rn(c, d);
    uint2 u;
    u.x = *(uint32_t*)&h01;
    u.y = *(uint32_t*)&h23;
    *(uint2*)dst = u;
}

// ---------------- fused prep: weight->half + LN1->half ----------------
__global__ void prep_kernel(const float* __restrict__ w0, const float* __restrict__ w1,
                            const float* __restrict__ w2, const float* __restrict__ w3,
                            __half* __restrict__ WT,
                            const float* __restrict__ x, const float* __restrict__ g,
                            const float* __restrict__ b, __half* __restrict__ out)
{
    if (blockIdx.x < W_BLOCKS) {
        int idx = blockIdx.x * 256 + threadIdx.x;
        if (idx >= W_TOTAL) return;
        float v;
        if (idx < W_QKV_N)                          v = w0[idx];
        else if (idx < W_QKV_N + W_PROJ_N)          v = w1[idx - W_QKV_N];
        else if (idx < W_QKV_N + W_PROJ_N + W_W1_N) v = w2[idx - W_QKV_N - W_PROJ_N];
        else                                        v = w3[idx - W_QKV_N - W_PROJ_N - W_W1_N];
        WT[idx] = __float2half_rn(v);
        return;
    }
    int gwarp = ((blockIdx.x - W_BLOCKS) * 256 + threadIdx.x) >> 5;
    int lane  = threadIdx.x & 31;
    if (gwarp >= NTOK) return;
    float4 v = ((const float4*)(x + (size_t)gwarp * CDIM))[lane];
    float s  = v.x + v.y + v.z + v.w;
    float ss = v.x*v.x + v.y*v.y + v.z*v.z + v.w*v.w;
    #pragma unroll
    for (int off = 16; off; off >>= 1) {
        s  += __shfl_xor_sync(0xffffffffu, s,  off);
        ss += __shfl_xor_sync(0xffffffffu, ss, off);
    }
    float mean = s * (1.0f / CDIM);
    float var  = ss * (1.0f / CDIM) - mean * mean;
    float rstd = rsqrtf(var + 1e-5f);
    float4 gg = ((const float4*)g)[lane];
    float4 bb = ((const float4*)b)[lane];
    store_half4(out + (size_t)gwarp * CDIM + lane * 4,
                (v.x - mean) * rstd * gg.x + bb.x,
                (v.y - mean) * rstd * gg.y + bb.y,
                (v.z - mean) * rstd * gg.z + bb.z,
                (v.w - mean) * rstd * gg.w + bb.w);
}

// ---------------- fp16 WMMA GEMM: C = epi(A @ B + bias) -------------------
// CTA tile 128x128, 8 warps (2M x 4N), warp tile 64x32 (4x2 of m16n16k16).
// K-chunks of 32, double-buffered cp.async. 2 CTAs/SM -> 16 warps/SM.
enum { EPI_BIAS = 0, EPI_BIAS_RES = 1, EPI_GELU = 2, EPI_RES_LN2 = 3 };

#define AH_STRIDE 40    // halves
#define BH_STRIDE 136   // halves
#define C_STRIDE  132   // floats (epilogue staging)
#define ABUFH (128 * AH_STRIDE * 2)     // 10240 B
#define BBUFH (32 * BH_STRIDE * 2)      // 8704 B
#define SMEM_BYTES (128 * C_STRIDE * 4) // 67584 B (epilogue dominates)

template <int EPI>
__global__ void __launch_bounds__(256, 2)
tc_gemm(const __half* __restrict__ A, const __half* __restrict__ B,
        const float* __restrict__ bias, const float* __restrict__ res,
        float* __restrict__ Cf, __half* __restrict__ Ch, int N, int K,
        const float* __restrict__ lng, const float* __restrict__ lnb,
        __half* __restrict__ C2)
{
    extern __shared__ char smem[];
    uint32_t sbase = smem_u32(smem);
    const int tid = threadIdx.x;
    const int wid = tid >> 5;
    const int warpM = wid & 1;          // 0..1 -> 64 rows
    const int warpN = wid >> 1;         // 0..3 -> 32 cols
    const int M0 = blockIdx.y * 128;
    const int N0 = blockIdx.x * 128;

    const __half* Abase = A + (size_t)M0 * K;
    const __half* Bbase = B + N0;
    const int nchunk = K >> 5;

    wmma::fragment<wmma::accumulator, 16, 16, 16, float> acc[4][2];
    #pragma unroll
    for (int i = 0; i < 4; i++)
        #pragma unroll
        for (int j = 0; j < 2; j++) wmma::fill_fragment(acc[i][j], 0.0f);

    auto load_chunk = [&](int c) {
        int buf = c & 1;
        uint32_t sa = sbase + buf * ABUFH;
        uint32_t sb = sbase + 2 * ABUFH + buf * BBUFH;
        int k0 = c << 5;
        #pragma unroll
        for (int q = 0; q < 2; q++) {       // A: 512 x 16B chunks
            int e = tid + q * 256;
            int row = e >> 2, c8 = (e & 3) * 8;
            cp_async16(sa + (row * AH_STRIDE + c8) * 2,
                       Abase + (size_t)row * K + k0 + c8);
        }
        #pragma unroll
        for (int q = 0; q < 2; q++) {       // B: 512 x 16B chunks
            int e = tid + q * 256;
            int row = e >> 4, c8 = (e & 15) * 8;
            cp_async16(sb + (row * BH_STRIDE + c8) * 2,
                       Bbase + (size_t)(k0 + row) * N + c8);
        }
    };

    load_chunk(0);
    CP_COMMIT();

    for (int c = 0; c < nchunk; c++) {
        if (c + 1 < nchunk) {
            load_chunk(c + 1);
            CP_COMMIT();
            CP_WAIT(1);
        } else {
            CP_WAIT(0);
        }
        __syncthreads();

        int buf = c & 1;
        const __half* As = (const __half*)(smem + buf * ABUFH);
        const __half* Bs = (const __half*)(smem + 2 * ABUFH + buf * BBUFH);
        #pragma unroll
        for (int ks = 0; ks < 2; ks++) {
            wmma::fragment<wmma::matrix_a, 16, 16, 16, __half, wmma::row_major> af[4];
            wmma::fragment<wmma::matrix_b, 16, 16, 16, __half, wmma::row_major> bf[2];
            #pragma unroll
            for (int i = 0; i < 4; i++)
                wmma::load_matrix_sync(af[i],
                    As + (warpM * 64 + i * 16) * AH_STRIDE + ks * 16, AH_STRIDE);
            #pragma unroll
            for (int j = 0; j < 2; j++)
                wmma::load_matrix_sync(bf[j],
                    Bs + (ks * 16) * BH_STRIDE + warpN * 32 + j * 16, BH_STRIDE);
            #pragma unroll
            for (int i = 0; i < 4; i++)
                #pragma unroll
                for (int j = 0; j < 2; j++)
                    wmma::mma_sync(acc[i][j], af[i], bf[j], acc[i][j]);
        }
        __syncthreads();
    }

    // stage accumulators in smem (fp32)
    float* Cs = (float*)smem;
    #pragma unroll
    for (int i = 0; i < 4; i++)
        #pragma unroll
        for (int j = 0; j < 2; j++)
            wmma::store_matrix_sync(
                Cs + (warpM * 64 + i * 16) * C_STRIDE + warpN * 32 + j * 16,
                acc[i][j], C_STRIDE, wmma::mem_row_major);
    __syncthreads();

    #pragma unroll
    for (int e0 = 0; e0 < 16; e0++) {
        int e = tid + e0 * 256;
        int row = e >> 5;
        int c4  = (e & 31) * 4;
        size_t roff = (size_t)(M0 + row) * N + N0 + c4;
        float v[4];
        #pragma unroll
        for (int q = 0; q < 4; q++) {
            float t = Cs[row * C_STRIDE + c4 + q] + __ldg(bias + N0 + c4 + q);
            if (EPI == EPI_BIAS_RES || EPI == EPI_RES_LN2) t += res[roff + q];
            if (EPI == EPI_GELU)
                t = 0.5f * t * (1.0f + erff(t * 0.70710678118654752f));
            v[q] = t;
        }
        if (EPI == EPI_GELU || EPI == EPI_BIAS) {
            store_half4(Ch + roff, v[0], v[1], v[2], v[3]);
        } else {
            *(float4*)(Cf + roff) = *(float4*)v;
        }
        if (EPI == EPI_RES_LN2) {
            // N==128: each warp's 128 values are one whole token row.
            float s  = v[0] + v[1] + v[2] + v[3];
            float ss = v[0]*v[0] + v[1]*v[1] + v[2]*v[2] + v[3]*v[3];
            #pragma unroll
            for (int off = 16; off; off >>= 1) {
                s  += __shfl_xor_sync(0xffffffffu, s,  off);
                ss += __shfl_xor_sync(0xffffffffu, ss, off);
            }
            float mean = s * (1.0f / CDIM);
            float var  = ss * (1.0f / CDIM) - mean * mean;
            float rstd = rsqrtf(var + 1e-5f);
            store_half4(C2 + roff,
                        (v[0] - mean) * rstd * __ldg(lng + c4 + 0) + __ldg(lnb + c4 + 0),
                        (v[1] - mean) * rstd * __ldg(lng + c4 + 1) + __ldg(lnb + c4 + 1),
                        (v[2] - mean) * rstd * __ldg(lng + c4 + 2) + __ldg(lnb + c4 + 2),
                        (v[3] - mean) * rstd * __ldg(lng + c4 + 3) + __ldg(lnb + c4 + 3));
        }
    }
}

// ---------------- windowed attention (uint4 gather) --------------
#define QS_STRIDE 36
#define S_STRIDE  50

__global__ __launch_bounds__(256)
void attn_kernel(const __half* __restrict__ qkv, __half* __restrict__ o)
{
    int blk  = blockIdx.x;
    int head = blk & 3;
    int w    = blk >> 2;
    int bimg = w >> 6;
    int win  = w & 63;
    int wr   = win >> 3, wc = win & 7;

    __shared__ int tok[TWIN];
    __shared__ __align__(16) float qs[52 * QS_STRIDE];
    __shared__ __align__(16) float ks[50 * QS_STRIDE];
    __shared__ __align__(16) float vs[49 * QS_STRIDE];
    __shared__ __align__(16) float S[52 * S_STRIDE];

    int tid = threadIdx.x;
    if (tid < TWIN) {
        int r = tid / WS, c = tid - r * WS;
        tok[tid] = bimg * (RESO * RESO) + (wr * WS + r) * RESO + (wc * WS + c);
    }
    if (tid < 3 * QS_STRIDE) qs[49 * QS_STRIDE + tid] = 0.0f;
    if (tid >= 128 && tid < 128 + QS_STRIDE) ks[49 * QS_STRIDE + (tid - 128)] = 0.0f;
    __syncthreads();

    // gather q,k,v with uint4 (8 halves) loads: 49 tokens x 4 chunks x 3 = 588
    for (int idx = tid; idx < TWIN * 4 * 3; idx += 256) {
        int which = idx / (TWIN * 4);
        int rem   = idx - which * (TWIN * 4);
        int t = rem >> 2, u = rem & 3;
        uint4 hv = *(const uint4*)(qkv + (size_t)tok[t] * (3 * CDIM)
                                   + which * CDIM + head * HDIM + u * 8);
        const __half2* hp = (const __half2*)&hv;
        float2 f0 = __half22float2(hp[0]);
        float2 f1 = __half22float2(hp[1]);
        float2 f2 = __half22float2(hp[2]);
        float2 f3 = __half22float2(hp[3]);
        float* dst = (which == 0) ? qs : (which == 1) ? ks : vs;
        float* p = dst + t * QS_STRIDE + u * 8;
        *(float4*)(p)     = make_float4(f0.x, f0.y, f1.x, f1.y);
        *(float4*)(p + 4) = make_float4(f2.x, f2.y, f3.x, f3.y);
    }
    __syncthreads();

    const float scale = 0.17677669529663687f;
    for (int t = tid; t < 13 * 25; t += 256) {
        int qg = t / 25, kg = t - qg * 25;
        int qi0 = qg * 4, ki0 = kg * 2;
        float a[4][2];
        #pragma unroll
        for (int i = 0; i < 4; i++) { a[i][0] = 0.0f; a[i][1] = 0.0f; }
        #pragma unroll
        for (int dq = 0; dq < 8; dq++) {
            float4 k0 = *(const float4*)&ks[ki0 * QS_STRIDE + 4 * dq];
            float4 k1 = *(const float4*)&ks[(ki0 + 1) * QS_STRIDE + 4 * dq];
            #pragma unroll
            for (int i = 0; i < 4; i++) {
                float4 q = *(const float4*)&qs[(qi0 + i) * QS_STRIDE + 4 * dq];
                a[i][0] = fmaf(q.x, k0.x, fmaf(q.y, k0.y, fmaf(q.z, k0.z, fmaf(q.w, k0.w, a[i][0]))));
                a[i][1] = fmaf(q.x, k1.x, fmaf(q.y, k1.y, fmaf(q.z, k1.z, fmaf(q.w, k1.w, a[i][1]))));
            }
        }
        #pragma unroll
        for (int i = 0; i < 4; i++)
            if (qi0 + i < TWIN)
                #pragma unroll
                for (int j = 0; j < 2; j++)
                    if (ki0 + j < TWIN)
                        S[(qi0 + i) * S_STRIDE + ki0 + j] = a[i][j] * scale;
    }
    __syncthreads();

    int warp = tid >> 5, lane = tid & 31;
    for (int row = warp; row < TWIN; row += 8) {
        float v0 = S[row * S_STRIDE + lane];
        float v1 = (lane + 32 < TWIN) ? S[row * S_STRIDE + lane + 32] : -3.4e38f;
        float m = fmaxf(v0, v1);
        #pragma unroll
        for (int off = 16; off; off >>= 1)
            m = fmaxf(m, __shfl_xor_sync(0xffffffffu, m, off));
        float e0 = __expf(v0 - m);
        float e1 = (lane + 32 < TWIN) ? __expf(v1 - m) : 0.0f;
        float s = e0 + e1;
        #pragma unroll
        for (int off = 16; off; off >>= 1)
            s += __shfl_xor_sync(0xffffffffu, s, off);
        float inv = 1.0f / s;
        S[row * S_STRIDE + lane] = e0 * inv;
        if (lane + 32 < TWIN) S[row * S_STRIDE + lane + 32] = e1 * inv;
    }
    __syncthreads();

    for (int t = tid; t < 13 * 16; t += 256) {
        int qg = t / 16, dp = t - qg * 16;
        int qi0 = qg * 4, d = dp * 2;
        float ax0 = 0, ay0 = 0, ax1 = 0, ay1 = 0,
              ax2 = 0, ay2 = 0, ax3 = 0, ay3 = 0;
        for (int ki = 0; ki < TWIN; ki++) {
            float2 vv = *(const float2*)&vs[ki * QS_STRIDE + d];
            float s0 = S[(qi0 + 0) * S_STRIDE + ki];
            float s1 = S[(qi0 + 1) * S_STRIDE + ki];
            float s2 = S[(qi0 + 2) * S_STRIDE + ki];
            float s3 = S[(qi0 + 3) * S_STRIDE + ki];
            ax0 = fmaf(s0, vv.x, ax0); ay0 = fmaf(s0, vv.y, ay0);
            ax1 = fmaf(s1, vv.x, ax1); ay1 = fmaf(s1, vv.y, ay1);
            ax2 = fmaf(s2, vv.x, ax2); ay2 = fmaf(s2, vv.y, ay2);
            ax3 = fmaf(s3, vv.x, ax3); ay3 = fmaf(s3, vv.y, ay3);
        }
        float axs[4] = {ax0, ax1, ax2, ax3};
        float ays[4] = {ay0, ay1, ay2, ay3};
        #pragma unroll
        for (int i = 0; i < 4; i++) {
            if (qi0 + i < TWIN) {
                __half2 p = __floats2half2_rn(axs[i], ays[i]);
                *(__half2*)(o + (size_t)tok[qi0 + i] * CDIM + head * HDIM + d) = p;
            }
        }
    }
}

// ---------------- launch ----------------
extern "C" void kernel_launch(void* const* d_in, const int* in_sizes, int n_in,
                              void* d_out, int out_size)
{
    const float* x      = (const float*)d_in[0];
    const float* ln1_g  = (const float*)d_in[1];
    const float* ln1_b  = (const float*)d_in[2];
    const float* qkv_w  = (const float*)d_in[3];
    const float* qkv_b  = (const float*)d_in[4];
    const float* proj_w = (const float*)d_in[5];
    const float* proj_b = (const float*)d_in[6];
    const float* ln2_g  = (const float*)d_in[7];
    const float* ln2_b  = (const float*)d_in[8];
    const float* mlp_w1 = (const float*)d_in[9];
    const float* mlp_b1 = (const float*)d_in[10];
    const float* mlp_w2 = (const float*)d_in[11];
    const float* mlp_b2 = (const float*)d_in[12];
    float* out = (float*)d_out;

    __half *p_lnh, *p_qkvh, *p_oh, *p_h1h, *p_wTh;
    float *p_x2;
    cudaGetSymbolAddress((void**)&p_lnh,  g_lnh);
    cudaGetSymbolAddress((void**)&p_qkvh, g_qkvh);
    cudaGetSymbolAddress((void**)&p_oh,   g_oh);
    cudaGetSymbolAddress((void**)&p_x2,   g_x2);
    cudaGetSymbolAddress((void**)&p_h1h,  g_h1h);
    cudaGetSymbolAddress((void**)&p_wTh,  g_wTh);
    __half* wt_qkv  = p_wTh;
    __half* wt_proj = p_wTh + W_QKV_N;
    __half* wt_w1   = p_wTh + W_QKV_N + W_PROJ_N;
    __half* wt_w2   = p_wTh + W_QKV_N + W_PROJ_N + W_W1_N;

    cudaFuncSetAttribute(tc_gemm<EPI_BIAS>,     cudaFuncAttributeMaxDynamicSharedMemorySize, SMEM_BYTES);
    cudaFuncSetAttribute(tc_gemm<EPI_BIAS_RES>, cudaFuncAttributeMaxDynamicSharedMemorySize, SMEM_BYTES);
    cudaFuncSetAttribute(tc_gemm<EPI_GELU>,     cudaFuncAttributeMaxDynamicSharedMemorySize, SMEM_BYTES);
    cudaFuncSetAttribute(tc_gemm<EPI_RES_LN2>,  cudaFuncAttributeMaxDynamicSharedMemorySize, SMEM_BYTES);

    const int MT = NTOK / 128;  // 784

    // 0. fused prep: weight->half + LN1->half
    prep_kernel<<<W_BLOCKS + LN_BLOCKS, 256>>>(qkv_w, proj_w, mlp_w1, mlp_w2, p_wTh,
                                               x, ln1_g, ln1_b, p_lnh);
    // 1. QKV = ln1 @ qkv_w + qkv_b  -> half
    tc_gemm<EPI_BIAS><<<dim3(3, MT), 256, SMEM_BYTES>>>(
        p_lnh, wt_qkv, qkv_b, nullptr, nullptr, p_qkvh, 3 * CDIM, CDIM,
        nullptr, nullptr, nullptr);
    // 2. attention (half in, half out)
    attn_kernel<<<NWIN * NHEAD, 256>>>(p_qkvh, p_oh);
    // 3. x2 = x + proj(o)  (fp32) ; fused LN2 -> half
    tc_gemm<EPI_RES_LN2><<<dim3(1, MT), 256, SMEM_BYTES>>>(
        p_oh, wt_proj, proj_b, x, p_x2, nullptr, CDIM, CDIM,
        ln2_g, ln2_b, p_lnh);
    // 4. h1 = gelu(ln2 @ w1 + b1) -> half
    tc_gemm<EPI_GELU><<<dim3(4, MT), 256, SMEM_BYTES>>>(
        p_lnh, wt_w1, mlp_b1, nullptr, nullptr, p_h1h, HID, CDIM,
        nullptr, nullptr, nullptr);
    // 5. out = x2 + h1 @ w2 + b2  (fp32)
    tc_gemm<EPI_BIAS_RES><<<dim3(1, MT), 256, SMEM_BYTES>>>(
        p_h1h, wt_w2, mlp_b2, p_x2, out, nullptr, CDIM, HID,
        nullptr, nullptr, nullptr);
}

// round 12
// speedup vs baseline: 2.4897x; 1.0455x over previous
#include <cuda_runtime.h>
#include <cuda_fp16.h>
#include <mma.h>
#include <math.h>
#include <stdint.h>

using namespace nvcuda;

// ---------------- problem constants ----------------
#define RESO 56
#define WS   7
#define CDIM 128
#define NHEAD 4
#define HDIM 32
#define HID  512
#define BATCH 32
#define NTOK (BATCH * RESO * RESO)      // 100352
#define NWIN (BATCH * 8 * 8)            // 2048 windows
#define TWIN 49

#define W_QKV_N 49152
#define W_PROJ_N 16384
#define W_W1_N 65536
#define W_W2_N 65536
#define W_TOTAL (W_QKV_N + W_PROJ_N + W_W1_N + W_W2_N)
#define W_BLOCKS ((W_TOTAL + 255) / 256)          // 769
#define LN_BLOCKS ((NTOK * 32) / 256)             // 12544

// ---------------- device scratch ----------------
__device__ __half g_lnh[(size_t)NTOK * CDIM];
__device__ __half g_qkvh[(size_t)NTOK * 3 * CDIM];
__device__ __half g_oh [(size_t)NTOK * CDIM];
__device__ float  g_x2 [(size_t)NTOK * CDIM];
__device__ __half g_h1h[(size_t)NTOK * HID];
__device__ __half g_wTh[W_TOTAL];

__device__ __forceinline__ uint32_t smem_u32(const void* p) {
    uint32_t a;
    asm("{ .reg .u64 t; cvta.to.shared.u64 t, %1; cvt.u32.u64 %0, t; }" : "=r"(a) : "l"(p));
    return a;
}
__device__ __forceinline__ void cp_async16(uint32_t saddr, const void* gaddr) {
    asm volatile("cp.async.ca.shared.global [%0], [%1], 16;" :: "r"(saddr), "l"(gaddr));
}
#define CP_COMMIT() asm volatile("cp.async.commit_group;" ::: "memory")
#define CP_WAIT(n)  asm volatile("cp.async.wait_group %0;" :: "n"(n) : "memory")

__device__ __forceinline__ void store_half4(__half* dst, float a, float b, float c, float d) {
    __half2 h01 = __floats2half2_rn(a, b);
    __half2 h23 = __floats2half2_rn(c, d);
    uint2 u;
    u.x = *(uint32_t*)&h01;
    u.y = *(uint32_t*)&h23;
    *(uint2*)dst = u;
}

// ---------------- fused prep: weight->half + LN1->half ----------------
__global__ void prep_kernel(const float* __restrict__ w0, const float* __restrict__ w1,
                            const float* __restrict__ w2, const float* __restrict__ w3,
                            __half* __restrict__ WT,
                            const float* __restrict__ x, const float* __restrict__ g,
                            const float* __restrict__ b, __half* __restrict__ out)
{
    if (blockIdx.x < W_BLOCKS) {
        int idx = blockIdx.x * 256 + threadIdx.x;
        if (idx >= W_TOTAL) return;
        float v;
        if (idx < W_QKV_N)                          v = w0[idx];
        else if (idx < W_QKV_N + W_PROJ_N)          v = w1[idx - W_QKV_N];
        else if (idx < W_QKV_N + W_PROJ_N + W_W1_N) v = w2[idx - W_QKV_N - W_PROJ_N];
        else                                        v = w3[idx - W_QKV_N - W_PROJ_N - W_W1_N];
        WT[idx] = __float2half_rn(v);
        return;
    }
    int gwarp = ((blockIdx.x - W_BLOCKS) * 256 + threadIdx.x) >> 5;
    int lane  = threadIdx.x & 31;
    if (gwarp >= NTOK) return;
    float4 v = ((const float4*)(x + (size_t)gwarp * CDIM))[lane];
    float s  = v.x + v.y + v.z + v.w;
    float ss = v.x*v.x + v.y*v.y + v.z*v.z + v.w*v.w;
    #pragma unroll
    for (int off = 16; off; off >>= 1) {
        s  += __shfl_xor_sync(0xffffffffu, s,  off);
        ss += __shfl_xor_sync(0xffffffffu, ss, off);
    }
    float mean = s * (1.0f / CDIM);
    float var  = ss * (1.0f / CDIM) - mean * mean;
    float rstd = rsqrtf(var + 1e-5f);
    float4 gg = ((const float4*)g)[lane];
    float4 bb = ((const float4*)b)[lane];
    store_half4(out + (size_t)gwarp * CDIM + lane * 4,
                (v.x - mean) * rstd * gg.x + bb.x,
                (v.y - mean) * rstd * gg.y + bb.y,
                (v.z - mean) * rstd * gg.z + bb.z,
                (v.w - mean) * rstd * gg.w + bb.w);
}

// ---------------- fp16 WMMA GEMM (R11 proven) -----------------------------
enum { EPI_BIAS = 0, EPI_BIAS_RES = 1, EPI_GELU = 2, EPI_RES_LN2 = 3 };

#define AH_STRIDE 40
#define BH_STRIDE 136
#define C_STRIDE  132
#define ABUFH (128 * AH_STRIDE * 2)     // 10240 B
#define BBUFH (32 * BH_STRIDE * 2)      // 8704 B
#define SMEM_BYTES (128 * C_STRIDE * 4) // 67584 B

template <int EPI>
__global__ void __launch_bounds__(256, 2)
tc_gemm(const __half* __restrict__ A, const __half* __restrict__ B,
        const float* __restrict__ bias, const float* __restrict__ res,
        float* __restrict__ Cf, __half* __restrict__ Ch, int N, int K,
        const float* __restrict__ lng, const float* __restrict__ lnb,
        __half* __restrict__ C2)
{
    extern __shared__ char smem[];
    uint32_t sbase = smem_u32(smem);
    const int tid = threadIdx.x;
    const int wid = tid >> 5;
    const int warpM = wid & 1;
    const int warpN = wid >> 1;
    const int M0 = blockIdx.y * 128;
    const int N0 = blockIdx.x * 128;

    const __half* Abase = A + (size_t)M0 * K;
    const __half* Bbase = B + N0;
    const int nchunk = K >> 5;

    wmma::fragment<wmma::accumulator, 16, 16, 16, float> acc[4][2];
    #pragma unroll
    for (int i = 0; i < 4; i++)
        #pragma unroll
        for (int j = 0; j < 2; j++) wmma::fill_fragment(acc[i][j], 0.0f);

    auto load_chunk = [&](int c) {
        int buf = c & 1;
        uint32_t sa = sbase + buf * ABUFH;
        uint32_t sb = sbase + 2 * ABUFH + buf * BBUFH;
        int k0 = c << 5;
        #pragma unroll
        for (int q = 0; q < 2; q++) {
            int e = tid + q * 256;
            int row = e >> 2, c8 = (e & 3) * 8;
            cp_async16(sa + (row * AH_STRIDE + c8) * 2,
                       Abase + (size_t)row * K + k0 + c8);
        }
        #pragma unroll
        for (int q = 0; q < 2; q++) {
            int e = tid + q * 256;
            int row = e >> 4, c8 = (e & 15) * 8;
            cp_async16(sb + (row * BH_STRIDE + c8) * 2,
                       Bbase + (size_t)(k0 + row) * N + c8);
        }
    };

    load_chunk(0);
    CP_COMMIT();

    for (int c = 0; c < nchunk; c++) {
        if (c + 1 < nchunk) {
            load_chunk(c + 1);
            CP_COMMIT();
            CP_WAIT(1);
        } else {
            CP_WAIT(0);
        }
        __syncthreads();

        int buf = c & 1;
        const __half* As = (const __half*)(smem + buf * ABUFH);
        const __half* Bs = (const __half*)(smem + 2 * ABUFH + buf * BBUFH);
        #pragma unroll
        for (int ks = 0; ks < 2; ks++) {
            wmma::fragment<wmma::matrix_a, 16, 16, 16, __half, wmma::row_major> af[4];
            wmma::fragment<wmma::matrix_b, 16, 16, 16, __half, wmma::row_major> bf[2];
            #pragma unroll
            for (int i = 0; i < 4; i++)
                wmma::load_matrix_sync(af[i],
                    As + (warpM * 64 + i * 16) * AH_STRIDE + ks * 16, AH_STRIDE);
            #pragma unroll
            for (int j = 0; j < 2; j++)
                wmma::load_matrix_sync(bf[j],
                    Bs + (ks * 16) * BH_STRIDE + warpN * 32 + j * 16, BH_STRIDE);
            #pragma unroll
            for (int i = 0; i < 4; i++)
                #pragma unroll
                for (int j = 0; j < 2; j++)
                    wmma::mma_sync(acc[i][j], af[i], bf[j], acc[i][j]);
        }
        __syncthreads();
    }

    float* Cs = (float*)smem;
    #pragma unroll
    for (int i = 0; i < 4; i++)
        #pragma unroll
        for (int j = 0; j < 2; j++)
            wmma::store_matrix_sync(
                Cs + (warpM * 64 + i * 16) * C_STRIDE + warpN * 32 + j * 16,
                acc[i][j], C_STRIDE, wmma::mem_row_major);
    __syncthreads();

    #pragma unroll
    for (int e0 = 0; e0 < 16; e0++) {
        int e = tid + e0 * 256;
        int row = e >> 5;
        int c4  = (e & 31) * 4;
        size_t roff = (size_t)(M0 + row) * N + N0 + c4;
        float v[4];
        #pragma unroll
        for (int q = 0; q < 4; q++) {
            float t = Cs[row * C_STRIDE + c4 + q] + __ldg(bias + N0 + c4 + q);
            if (EPI == EPI_BIAS_RES || EPI == EPI_RES_LN2) t += res[roff + q];
            if (EPI == EPI_GELU)
                t = 0.5f * t * (1.0f + erff(t * 0.70710678118654752f));
            v[q] = t;
        }
        if (EPI == EPI_GELU || EPI == EPI_BIAS) {
            store_half4(Ch + roff, v[0], v[1], v[2], v[3]);
        } else {
            *(float4*)(Cf + roff) = *(float4*)v;
        }
        if (EPI == EPI_RES_LN2) {
            float s  = v[0] + v[1] + v[2] + v[3];
            float ss = v[0]*v[0] + v[1]*v[1] + v[2]*v[2] + v[3]*v[3];
            #pragma unroll
            for (int off = 16; off; off >>= 1) {
                s  += __shfl_xor_sync(0xffffffffu, s,  off);
                ss += __shfl_xor_sync(0xffffffffu, ss, off);
            }
            float mean = s * (1.0f / CDIM);
            float var  = ss * (1.0f / CDIM) - mean * mean;
            float rstd = rsqrtf(var + 1e-5f);
            store_half4(C2 + roff,
                        (v[0] - mean) * rstd * __ldg(lng + c4 + 0) + __ldg(lnb + c4 + 0),
                        (v[1] - mean) * rstd * __ldg(lng + c4 + 1) + __ldg(lnb + c4 + 1),
                        (v[2] - mean) * rstd * __ldg(lng + c4 + 2) + __ldg(lnb + c4 + 2),
                        (v[3] - mean) * rstd * __ldg(lng + c4 + 3) + __ldg(lnb + c4 + 3));
        }
    }
}

// ---------------- tensor-core windowed attention ---------------------------
// One block per window (all 4 heads). T=49 padded to 64 rows. fp16 MMA for
// S = Q@K^T and O = P@V; fp32 softmax in smem.
// smem layout (bytes):
//   [0,256)        tok
//   [256,61696)    q/k/v halves: tensor*10240 + head*2560 + row*40 + d
//   [61696,79104)  Ss: 64 x 68 fp32 (S scores / O staging)
//   [79104,88320)  Ph: 64 x 72 half (probabilities)
#define ATT_SMEM 88320

__global__ void __launch_bounds__(256)
attn_kernel(const __half* __restrict__ qkv, __half* __restrict__ o)
{
    extern __shared__ char smc[];
    int*    tok = (int*)smc;
    __half* qh  = (__half*)(smc + 256);
    __half* kh  = qh + 10240;
    __half* vh  = qh + 20480;
    float*  Ss  = (float*)(smc + 61696);
    __half* Ph  = (__half*)(smc + 79104);

    int w = blockIdx.x;
    int bimg = w >> 6, win = w & 63;
    int wr = win >> 3, wc = win & 7;
    int tid = threadIdx.x, wid = tid >> 5, lane = tid & 31;

    if (tid < TWIN) {
        int r = tid / WS, c = tid - r * WS;
        tok[tid] = bimg * (RESO * RESO) + (wr * WS + r) * RESO + (wc * WS + c);
    }
    // zero padded rows 49..63 for q,k,v (all heads): 3*4*15*5 = 900 uint4
    for (int i = tid; i < 900; i += 256) {
        int u = i % 5;
        int row = 49 + (i / 5) % 15;
        int th = i / 75;
        int tensor = th >> 2, head = th & 3;
        *(uint4*)(qh + tensor * 10240 + head * 2560 + row * 40 + u * 8) =
            make_uint4(0, 0, 0, 0);
    }
    __syncthreads();

    // gather all heads: 49 tokens x 48 uint4 chunks
    for (int i = tid; i < TWIN * 48; i += 256) {
        int t = i / 48, c = i - t * 48;
        int tensor = c >> 4, head = (c >> 2) & 3, u = c & 3;
        uint4 hv = *(const uint4*)(qkv + (size_t)tok[t] * 384
                                   + tensor * 128 + head * 32 + u * 8);
        *(uint4*)(qh + tensor * 10240 + head * 2560 + t * 40 + u * 8) = hv;
    }
    __syncthreads();

    const float scale = 0.17677669529663687f;
    int wM = wid & 3;       // 16-row slice
    int wN = wid >> 2;      // 0..1

    for (int head = 0; head < NHEAD; head++) {
        const __half* q = qh + head * 2560;
        const __half* k = kh + head * 2560;
        const __half* v = vh + head * 2560;

        // S = Q @ K^T (64x64x32), scale folded into accumulator
        wmma::fragment<wmma::accumulator, 16, 16, 16, float> sa[2];
        wmma::fill_fragment(sa[0], 0.0f);
        wmma::fill_fragment(sa[1], 0.0f);
        #pragma unroll
        for (int kt = 0; kt < 2; kt++) {
            wmma::fragment<wmma::matrix_a, 16, 16, 16, __half, wmma::row_major> af;
            wmma::load_matrix_sync(af, q + (wM * 16) * 40 + kt * 16, 40);
            #pragma unroll
            for (int j = 0; j < 2; j++) {
                wmma::fragment<wmma::matrix_b, 16, 16, 16, __half, wmma::col_major> bf;
                wmma::load_matrix_sync(bf, k + (wN * 32 + j * 16) * 40 + kt * 16, 40);
                wmma::mma_sync(sa[j], af, bf, sa[j]);
            }
        }
        #pragma unroll
        for (int j = 0; j < 2; j++) {
            #pragma unroll
            for (int e = 0; e < sa[j].num_elements; e++) sa[j].x[e] *= scale;
            wmma::store_matrix_sync(Ss + (wM * 16) * 68 + wN * 32 + j * 16,
                                    sa[j], 68, wmma::mem_row_major);
        }
        __syncthreads();

        // softmax per real row (49), fp32
        for (int row = wid; row < TWIN; row += 8) {
            float v0 = Ss[row * 68 + lane];
            float v1 = (lane + 32 < TWIN) ? Ss[row * 68 + lane + 32] : -3.4e38f;
            float m = fmaxf(v0, v1);
            #pragma unroll
            for (int off = 16; off; off >>= 1)
                m = fmaxf(m, __shfl_xor_sync(0xffffffffu, m, off));
            float e0 = __expf(v0 - m);
            float e1 = (lane + 32 < TWIN) ? __expf(v1 - m) : 0.0f;
            float s = e0 + e1;
            #pragma unroll
            for (int off = 16; off; off >>= 1)
                s += __shfl_xor_sync(0xffffffffu, s, off);
            float inv = 1.0f / s;
            Ss[row * 68 + lane] = e0 * inv;
            if (lane + 32 < TWIN) Ss[row * 68 + lane + 32] = e1 * inv;
        }
        __syncthreads();

        // convert P -> half (zero cols >= 49)
        for (int e = tid; e < 2048; e += 256) {
            int r = e >> 5, c = (e & 31) * 2;
            float f0 = (c < TWIN)     ? Ss[r * 68 + c]     : 0.0f;
            float f1 = (c + 1 < TWIN) ? Ss[r * 68 + c + 1] : 0.0f;
            *(__half2*)(Ph + r * 72 + c) = __floats2half2_rn(f0, f1);
        }
        __syncthreads();

        // O = P @ V (64x32x64)
        wmma::fragment<wmma::accumulator, 16, 16, 16, float> oa;
        wmma::fill_fragment(oa, 0.0f);
        #pragma unroll
        for (int kt = 0; kt < 4; kt++) {
            wmma::fragment<wmma::matrix_a, 16, 16, 16, __half, wmma::row_major> pf;
            wmma::fragment<wmma::matrix_b, 16, 16, 16, __half, wmma::row_major> vf;
            wmma::load_matrix_sync(pf, Ph + (wM * 16) * 72 + kt * 16, 72);
            wmma::load_matrix_sync(vf, v + (kt * 16) * 40 + wN * 16, 40);
            wmma::mma_sync(oa, pf, vf, oa);
        }
        wmma::store_matrix_sync(Ss + (wM * 16) * 68 + wN * 16, oa, 68,
                                wmma::mem_row_major);
        __syncthreads();

        // scatter output (49 rows x 32 dims)
        for (int e = tid; e < TWIN * 16; e += 256) {
            int r = e >> 4, d = (e & 15) * 2;
            __half2 p = __floats2half2_rn(Ss[r * 68 + d], Ss[r * 68 + d + 1]);
            *(__half2*)(o + (size_t)tok[r] * CDIM + head * HDIM + d) = p;
        }
        __syncthreads();
    }
}

// ---------------- launch ----------------
extern "C" void kernel_launch(void* const* d_in, const int* in_sizes, int n_in,
                              void* d_out, int out_size)
{
    const float* x      = (const float*)d_in[0];
    const float* ln1_g  = (const float*)d_in[1];
    const float* ln1_b  = (const float*)d_in[2];
    const float* qkv_w  = (const float*)d_in[3];
    const float* qkv_b  = (const float*)d_in[4];
    const float* proj_w = (const float*)d_in[5];
    const float* proj_b = (const float*)d_in[6];
    const float* ln2_g  = (const float*)d_in[7];
    const float* ln2_b  = (const float*)d_in[8];
    const float* mlp_w1 = (const float*)d_in[9];
    const float* mlp_b1 = (const float*)d_in[10];
    const float* mlp_w2 = (const float*)d_in[11];
    const float* mlp_b2 = (const float*)d_in[12];
    float* out = (float*)d_out;

    __half *p_lnh, *p_qkvh, *p_oh, *p_h1h, *p_wTh;
    float *p_x2;
    cudaGetSymbolAddress((void**)&p_lnh,  g_lnh);
    cudaGetSymbolAddress((void**)&p_qkvh, g_qkvh);
    cudaGetSymbolAddress((void**)&p_oh,   g_oh);
    cudaGetSymbolAddress((void**)&p_x2,   g_x2);
    cudaGetSymbolAddress((void**)&p_h1h,  g_h1h);
    cudaGetSymbolAddress((void**)&p_wTh,  g_wTh);
    __half* wt_qkv  = p_wTh;
    __half* wt_proj = p_wTh + W_QKV_N;
    __half* wt_w1   = p_wTh + W_QKV_N + W_PROJ_N;
    __half* wt_w2   = p_wTh + W_QKV_N + W_PROJ_N + W_W1_N;

    cudaFuncSetAttribute(tc_gemm<EPI_BIAS>,     cudaFuncAttributeMaxDynamicSharedMemorySize, SMEM_BYTES);
    cudaFuncSetAttribute(tc_gemm<EPI_BIAS_RES>, cudaFuncAttributeMaxDynamicSharedMemorySize, SMEM_BYTES);
    cudaFuncSetAttribute(tc_gemm<EPI_GELU>,     cudaFuncAttributeMaxDynamicSharedMemorySize, SMEM_BYTES);
    cudaFuncSetAttribute(tc_gemm<EPI_RES_LN2>,  cudaFuncAttributeMaxDynamicSharedMemorySize, SMEM_BYTES);
    cudaFuncSetAttribute(attn_kernel,           cudaFuncAttributeMaxDynamicSharedMemorySize, ATT_SMEM);

    const int MT = NTOK / 128;  // 784

    // 0. fused prep: weight->half + LN1->half
    prep_kernel<<<W_BLOCKS + LN_BLOCKS, 256>>>(qkv_w, proj_w, mlp_w1, mlp_w2, p_wTh,
                                               x, ln1_g, ln1_b, p_lnh);
    // 1. QKV = ln1 @ qkv_w + qkv_b  -> half
    tc_gemm<EPI_BIAS><<<dim3(3, MT), 256, SMEM_BYTES>>>(
        p_lnh, wt_qkv, qkv_b, nullptr, nullptr, p_qkvh, 3 * CDIM, CDIM,
        nullptr, nullptr, nullptr);
    // 2. attention (tensor cores; one block per window)
    attn_kernel<<<NWIN, 256, ATT_SMEM>>>(p_qkvh, p_oh);
    // 3. x2 = x + proj(o)  (fp32) ; fused LN2 -> half
    tc_gemm<EPI_RES_LN2><<<dim3(1, MT), 256, SMEM_BYTES>>>(
        p_oh, wt_proj, proj_b, x, p_x2, nullptr, CDIM, CDIM,
        ln2_g, ln2_b, p_lnh);
    // 4. h1 = gelu(ln2 @ w1 + b1) -> half
    tc_gemm<EPI_GELU><<<dim3(4, MT), 256, SMEM_BYTES>>>(
        p_lnh, wt_w1, mlp_b1, nullptr, nullptr, p_h1h, HID, CDIM,
        nullptr, nullptr, nullptr);
    // 5. out = x2 + h1 @ w2 + b2  (fp32)
    tc_gemm<EPI_BIAS_RES><<<dim3(1, MT), 256, SMEM_BYTES>>>(
        p_h1h, wt_w2, mlp_b2, p_x2, out, nullptr, CDIM, HID,
        nullptr, nullptr, nullptr);
}

// round 13
// speedup vs baseline: 2.6203x; 1.0525x over previous
#include <cuda_runtime.h>
#include <cuda_fp16.h>
#include <mma.h>
#include <math.h>
#include <stdint.h>

using namespace nvcuda;

// ---------------- problem constants ----------------
#define RESO 56
#define WS   7
#define CDIM 128
#define NHEAD 4
#define HDIM 32
#define HID  512
#define BATCH 32
#define NTOK (BATCH * RESO * RESO)      // 100352
#define NWIN (BATCH * 8 * 8)            // 2048 windows
#define TWIN 49

#define W_QKV_N 49152
#define W_PROJ_N 16384
#define W_W1_N 65536
#define W_W2_N 65536
#define W_TOTAL (W_QKV_N + W_PROJ_N + W_W1_N + W_W2_N)
#define W_BLOCKS ((W_TOTAL + 255) / 256)          // 769
#define LN_BLOCKS ((NTOK * 32) / 256)             // 12544

// ---------------- device scratch ----------------
__device__ __half g_lnh[(size_t)NTOK * CDIM];
__device__ __half g_qkvh[(size_t)NTOK * 3 * CDIM];
__device__ __half g_oh [(size_t)NTOK * CDIM];
__device__ __half g_x2h[(size_t)NTOK * CDIM];
__device__ __half g_h1h[(size_t)NTOK * HID];
__device__ __half g_wTh[W_TOTAL];

__device__ __forceinline__ uint32_t smem_u32(const void* p) {
    uint32_t a;
    asm("{ .reg .u64 t; cvta.to.shared.u64 t, %1; cvt.u32.u64 %0, t; }" : "=r"(a) : "l"(p));
    return a;
}
__device__ __forceinline__ void cp_async16(uint32_t saddr, const void* gaddr) {
    asm volatile("cp.async.ca.shared.global [%0], [%1], 16;" :: "r"(saddr), "l"(gaddr));
}
#define CP_COMMIT() asm volatile("cp.async.commit_group;" ::: "memory")
#define CP_WAIT(n)  asm volatile("cp.async.wait_group %0;" :: "n"(n) : "memory")

__device__ __forceinline__ void store_half4(__half* dst, float a, float b, float c, float d) {
    __half2 h01 = __floats2half2_rn(a, b);
    __half2 h23 = __floats2half2_rn(c, d);
    uint2 u;
    u.x = *(uint32_t*)&h01;
    u.y = *(uint32_t*)&h23;
    *(uint2*)dst = u;
}

// ---------------- fused prep: weight->half + LN1->half ----------------
__global__ void prep_kernel(const float* __restrict__ w0, const float* __restrict__ w1,
                            const float* __restrict__ w2, const float* __restrict__ w3,
                            __half* __restrict__ WT,
                            const float* __restrict__ x, const float* __restrict__ g,
                            const float* __restrict__ b, __half* __restrict__ out)
{
    if (blockIdx.x < W_BLOCKS) {
        int idx = blockIdx.x * 256 + threadIdx.x;
        if (idx >= W_TOTAL) return;
        float v;
        if (idx < W_QKV_N)                          v = w0[idx];
        else if (idx < W_QKV_N + W_PROJ_N)          v = w1[idx - W_QKV_N];
        else if (idx < W_QKV_N + W_PROJ_N + W_W1_N) v = w2[idx - W_QKV_N - W_PROJ_N];
        else                                        v = w3[idx - W_QKV_N - W_PROJ_N - W_W1_N];
        WT[idx] = __float2half_rn(v);
        return;
    }
    int gwarp = ((blockIdx.x - W_BLOCKS) * 256 + threadIdx.x) >> 5;
    int lane  = threadIdx.x & 31;
    if (gwarp >= NTOK) return;
    float4 v = ((const float4*)(x + (size_t)gwarp * CDIM))[lane];
    float s  = v.x + v.y + v.z + v.w;
    float ss = v.x*v.x + v.y*v.y + v.z*v.z + v.w*v.w;
    #pragma unroll
    for (int off = 16; off; off >>= 1) {
        s  += __shfl_xor_sync(0xffffffffu, s,  off);
        ss += __shfl_xor_sync(0xffffffffu, ss, off);
    }
    float mean = s * (1.0f / CDIM);
    float var  = ss * (1.0f / CDIM) - mean * mean;
    float rstd = rsqrtf(var + 1e-5f);
    float4 gg = ((const float4*)g)[lane];
    float4 bb = ((const float4*)b)[lane];
    store_half4(out + (size_t)gwarp * CDIM + lane * 4,
                (v.x - mean) * rstd * gg.x + bb.x,
                (v.y - mean) * rstd * gg.y + bb.y,
                (v.z - mean) * rstd * gg.z + bb.z,
                (v.w - mean) * rstd * gg.w + bb.w);
}

// ---------------- fp16 WMMA GEMM (R11 proven core) -------------------------
enum { EPI_BIAS = 0, EPI_GELU = 2, EPI_RES_LN2 = 3, EPI_BIAS_RESH = 4 };

#define AH_STRIDE 40
#define BH_STRIDE 136
#define C_STRIDE  132
#define ABUFH (128 * AH_STRIDE * 2)     // 10240 B
#define BBUFH (32 * BH_STRIDE * 2)      // 8704 B
#define SMEM_BYTES (128 * C_STRIDE * 4) // 67584 B

template <int EPI>
__global__ void __launch_bounds__(256, 2)
tc_gemm(const __half* __restrict__ A, const __half* __restrict__ B,
        const float* __restrict__ bias, const float* __restrict__ res,
        const __half* __restrict__ resh,
        float* __restrict__ Cf, __half* __restrict__ Ch, int N, int K,
        const float* __restrict__ lng, const float* __restrict__ lnb,
        __half* __restrict__ C2)
{
    extern __shared__ char smem[];
    uint32_t sbase = smem_u32(smem);
    const int tid = threadIdx.x;
    const int wid = tid >> 5;
    const int warpM = wid & 1;
    const int warpN = wid >> 1;
    const int M0 = blockIdx.y * 128;
    const int N0 = blockIdx.x * 128;

    const __half* Abase = A + (size_t)M0 * K;
    const __half* Bbase = B + N0;
    const int nchunk = K >> 5;

    wmma::fragment<wmma::accumulator, 16, 16, 16, float> acc[4][2];
    #pragma unroll
    for (int i = 0; i < 4; i++)
        #pragma unroll
        for (int j = 0; j < 2; j++) wmma::fill_fragment(acc[i][j], 0.0f);

    auto load_chunk = [&](int c) {
        int buf = c & 1;
        uint32_t sa = sbase + buf * ABUFH;
        uint32_t sb = sbase + 2 * ABUFH + buf * BBUFH;
        int k0 = c << 5;
        #pragma unroll
        for (int q = 0; q < 2; q++) {
            int e = tid + q * 256;
            int row = e >> 2, c8 = (e & 3) * 8;
            cp_async16(sa + (row * AH_STRIDE + c8) * 2,
                       Abase + (size_t)row * K + k0 + c8);
        }
        #pragma unroll
        for (int q = 0; q < 2; q++) {
            int e = tid + q * 256;
            int row = e >> 4, c8 = (e & 15) * 8;
            cp_async16(sb + (row * BH_STRIDE + c8) * 2,
                       Bbase + (size_t)(k0 + row) * N + c8);
        }
    };

    load_chunk(0);
    CP_COMMIT();

    for (int c = 0; c < nchunk; c++) {
        if (c + 1 < nchunk) {
            load_chunk(c + 1);
            CP_COMMIT();
            CP_WAIT(1);
        } else {
            CP_WAIT(0);
        }
        __syncthreads();

        int buf = c & 1;
        const __half* As = (const __half*)(smem + buf * ABUFH);
        const __half* Bs = (const __half*)(smem + 2 * ABUFH + buf * BBUFH);
        #pragma unroll
        for (int ks = 0; ks < 2; ks++) {
            wmma::fragment<wmma::matrix_a, 16, 16, 16, __half, wmma::row_major> af[4];
            wmma::fragment<wmma::matrix_b, 16, 16, 16, __half, wmma::row_major> bf[2];
            #pragma unroll
            for (int i = 0; i < 4; i++)
                wmma::load_matrix_sync(af[i],
                    As + (warpM * 64 + i * 16) * AH_STRIDE + ks * 16, AH_STRIDE);
            #pragma unroll
            for (int j = 0; j < 2; j++)
                wmma::load_matrix_sync(bf[j],
                    Bs + (ks * 16) * BH_STRIDE + warpN * 32 + j * 16, BH_STRIDE);
            #pragma unroll
            for (int i = 0; i < 4; i++)
                #pragma unroll
                for (int j = 0; j < 2; j++)
                    wmma::mma_sync(acc[i][j], af[i], bf[j], acc[i][j]);
        }
        __syncthreads();
    }

    float* Cs = (float*)smem;
    #pragma unroll
    for (int i = 0; i < 4; i++)
        #pragma unroll
        for (int j = 0; j < 2; j++)
            wmma::store_matrix_sync(
                Cs + (warpM * 64 + i * 16) * C_STRIDE + warpN * 32 + j * 16,
                acc[i][j], C_STRIDE, wmma::mem_row_major);
    __syncthreads();

    #pragma unroll
    for (int e0 = 0; e0 < 16; e0++) {
        int e = tid + e0 * 256;
        int row = e >> 5;
        int c4  = (e & 31) * 4;
        size_t roff = (size_t)(M0 + row) * N + N0 + c4;
        float rv[4] = {0, 0, 0, 0};
        if (EPI == EPI_BIAS_RESH) {
            uint2 ru = *(const uint2*)(resh + roff);
            float2 r0 = __half22float2(*(__half2*)&ru.x);
            float2 r1 = __half22float2(*(__half2*)&ru.y);
            rv[0] = r0.x; rv[1] = r0.y; rv[2] = r1.x; rv[3] = r1.y;
        }
        float v[4];
        #pragma unroll
        for (int q = 0; q < 4; q++) {
            float t = Cs[row * C_STRIDE + c4 + q] + __ldg(bias + N0 + c4 + q);
            if (EPI == EPI_RES_LN2) t += res[roff + q];
            if (EPI == EPI_BIAS_RESH) t += rv[q];
            if (EPI == EPI_GELU)
                t = 0.5f * t * (1.0f + erff(t * 0.70710678118654752f));
            v[q] = t;
        }
        if (EPI == EPI_BIAS_RESH) {
            *(float4*)(Cf + roff) = *(float4*)v;
        } else {
            store_half4(Ch + roff, v[0], v[1], v[2], v[3]);
        }
        if (EPI == EPI_RES_LN2) {
            float s  = v[0] + v[1] + v[2] + v[3];
            float ss = v[0]*v[0] + v[1]*v[1] + v[2]*v[2] + v[3]*v[3];
            #pragma unroll
            for (int off = 16; off; off >>= 1) {
                s  += __shfl_xor_sync(0xffffffffu, s,  off);
                ss += __shfl_xor_sync(0xffffffffu, ss, off);
            }
            float mean = s * (1.0f / CDIM);
            float var  = ss * (1.0f / CDIM) - mean * mean;
            float rstd = rsqrtf(var + 1e-5f);
            store_half4(C2 + roff,
                        (v[0] - mean) * rstd * __ldg(lng + c4 + 0) + __ldg(lnb + c4 + 0),
                        (v[1] - mean) * rstd * __ldg(lng + c4 + 1) + __ldg(lnb + c4 + 1),
                        (v[2] - mean) * rstd * __ldg(lng + c4 + 2) + __ldg(lnb + c4 + 2),
                        (v[3] - mean) * rstd * __ldg(lng + c4 + 3) + __ldg(lnb + c4 + 3));
        }
    }
}

// ---------------- tensor-core windowed attention ---------------------------
// One block per window (all 4 heads). fused scale+softmax+P->half.
#define ATT_SMEM 88320

__global__ void __launch_bounds__(256)
attn_kernel(const __half* __restrict__ qkv, __half* __restrict__ o)
{
    extern __shared__ char smc[];
    int*    tok = (int*)smc;
    __half* qh  = (__half*)(smc + 256);
    __half* kh  = qh + 10240;
    __half* vh  = qh + 20480;
    float*  Ss  = (float*)(smc + 61696);
    __half* Ph  = (__half*)(smc + 79104);

    int w = blockIdx.x;
    int bimg = w >> 6, win = w & 63;
    int wr = win >> 3, wc = win & 7;
    int tid = threadIdx.x, wid = tid >> 5, lane = tid & 31;

    if (tid < TWIN) {
        int r = tid / WS, c = tid - r * WS;
        tok[tid] = bimg * (RESO * RESO) + (wr * WS + r) * RESO + (wc * WS + c);
    }
    // zero padded rows 49..63 for q,k,v (all heads)
    for (int i = tid; i < 900; i += 256) {
        int u = i % 5;
        int row = 49 + (i / 5) % 15;
        int th = i / 75;
        int tensor = th >> 2, head = th & 3;
        *(uint4*)(qh + tensor * 10240 + head * 2560 + row * 40 + u * 8) =
            make_uint4(0, 0, 0, 0);
    }
    __syncthreads();

    // gather all heads: 49 tokens x 48 uint4 chunks
    for (int i = tid; i < TWIN * 48; i += 256) {
        int t = i / 48, c = i - t * 48;
        int tensor = c >> 4, head = (c >> 2) & 3, u = c & 3;
        uint4 hv = *(const uint4*)(qkv + (size_t)tok[t] * 384
                                   + tensor * 128 + head * 32 + u * 8);
        *(uint4*)(qh + tensor * 10240 + head * 2560 + t * 40 + u * 8) = hv;
    }
    __syncthreads();

    const float scale = 0.17677669529663687f;
    int wM = wid & 3;       // 16-row slice
    int wN = wid >> 2;      // 0..1

    for (int head = 0; head < NHEAD; head++) {
        const __half* q = qh + head * 2560;
        const __half* k = kh + head * 2560;
        const __half* v = vh + head * 2560;

        // S = Q @ K^T (64x64x32); raw scores to Ss
        wmma::fragment<wmma::accumulator, 16, 16, 16, float> sa[2];
        wmma::fill_fragment(sa[0], 0.0f);
        wmma::fill_fragment(sa[1], 0.0f);
        #pragma unroll
        for (int kt = 0; kt < 2; kt++) {
            wmma::fragment<wmma::matrix_a, 16, 16, 16, __half, wmma::row_major> af;
            wmma::load_matrix_sync(af, q + (wM * 16) * 40 + kt * 16, 40);
            #pragma unroll
            for (int j = 0; j < 2; j++) {
                wmma::fragment<wmma::matrix_b, 16, 16, 16, __half, wmma::col_major> bf;
                wmma::load_matrix_sync(bf, k + (wN * 32 + j * 16) * 40 + kt * 16, 40);
                wmma::mma_sync(sa[j], af, bf, sa[j]);
            }
        }
        #pragma unroll
        for (int j = 0; j < 2; j++)
            wmma::store_matrix_sync(Ss + (wM * 16) * 68 + wN * 32 + j * 16,
                                    sa[j], 68, wmma::mem_row_major);
        __syncthreads();

        // fused scale + softmax + half conversion -> Ph (zeroing pad cols)
        for (int row = wid; row < TWIN; row += 8) {
            float v0 = Ss[row * 68 + lane] * scale;
            float v1 = (lane + 32 < TWIN) ? Ss[row * 68 + lane + 32] * scale : -3.4e38f;
            float m = fmaxf(v0, v1);
            #pragma unroll
            for (int off = 16; off; off >>= 1)
                m = fmaxf(m, __shfl_xor_sync(0xffffffffu, m, off));
            float e0 = __expf(v0 - m);
            float e1 = (lane + 32 < TWIN) ? __expf(v1 - m) : 0.0f;
            float s = e0 + e1;
            #pragma unroll
            for (int off = 16; off; off >>= 1)
                s += __shfl_xor_sync(0xffffffffu, s, off);
            float inv = 1.0f / s;
            Ph[row * 72 + lane]      = __float2half_rn(e0 * inv);
            Ph[row * 72 + lane + 32] = __float2half_rn(e1 * inv);  // 0 for pad cols
        }
        // zero Ph pad rows only on first head (stale data could be NaN/huge;
        // keep MMA sane — rows 49..63 never scattered but cost nothing here)
        if (head == 0) {
            for (int e = tid; e < 15 * 16; e += 256) {
                int r = 49 + (e >> 4), c = (e & 15) * 4;
                *(uint2*)(Ph + r * 72 + c) = make_uint2(0, 0);
            }
        }
        __syncthreads();

        // O = P @ V (64x32x64)
        wmma::fragment<wmma::accumulator, 16, 16, 16, float> oa;
        wmma::fill_fragment(oa, 0.0f);
        #pragma unroll
        for (int kt = 0; kt < 4; kt++) {
            wmma::fragment<wmma::matrix_a, 16, 16, 16, __half, wmma::row_major> pf;
            wmma::fragment<wmma::matrix_b, 16, 16, 16, __half, wmma::row_major> vf;
            wmma::load_matrix_sync(pf, Ph + (wM * 16) * 72 + kt * 16, 72);
            wmma::load_matrix_sync(vf, v + (kt * 16) * 40 + wN * 16, 40);
            wmma::mma_sync(oa, pf, vf, oa);
        }
        wmma::store_matrix_sync(Ss + (wM * 16) * 68 + wN * 16, oa, 68,
                                wmma::mem_row_major);
        __syncthreads();

        // scatter output (49 rows x 32 dims)
        for (int e = tid; e < TWIN * 16; e += 256) {
            int r = e >> 4, d = (e & 15) * 2;
            __half2 p = __floats2half2_rn(Ss[r * 68 + d], Ss[r * 68 + d + 1]);
            *(__half2*)(o + (size_t)tok[r] * CDIM + head * HDIM + d) = p;
        }
        __syncthreads();
    }
}

// ---------------- launch ----------------
extern "C" void kernel_launch(void* const* d_in, const int* in_sizes, int n_in,
                              void* d_out, int out_size)
{
    const float* x      = (const float*)d_in[0];
    const float* ln1_g  = (const float*)d_in[1];
    const float* ln1_b  = (const float*)d_in[2];
    const float* qkv_w  = (const float*)d_in[3];
    const float* qkv_b  = (const float*)d_in[4];
    const float* proj_w = (const float*)d_in[5];
    const float* proj_b = (const float*)d_in[6];
    const float* ln2_g  = (const float*)d_in[7];
    const float* ln2_b  = (const float*)d_in[8];
    const float* mlp_w1 = (const float*)d_in[9];
    const float* mlp_b1 = (const float*)d_in[10];
    const float* mlp_w2 = (const float*)d_in[11];
    const float* mlp_b2 = (const float*)d_in[12];
    float* out = (float*)d_out;

    __half *p_lnh, *p_qkvh, *p_oh, *p_x2h, *p_h1h, *p_wTh;
    cudaGetSymbolAddress((void**)&p_lnh,  g_lnh);
    cudaGetSymbolAddress((void**)&p_qkvh, g_qkvh);
    cudaGetSymbolAddress((void**)&p_oh,   g_oh);
    cudaGetSymbolAddress((void**)&p_x2h,  g_x2h);
    cudaGetSymbolAddress((void**)&p_h1h,  g_h1h);
    cudaGetSymbolAddress((void**)&p_wTh,  g_wTh);
    __half* wt_qkv  = p_wTh;
    __half* wt_proj = p_wTh + W_QKV_N;
    __half* wt_w1   = p_wTh + W_QKV_N + W_PROJ_N;
    __half* wt_w2   = p_wTh + W_QKV_N + W_PROJ_N + W_W1_N;

    cudaFuncSetAttribute(tc_gemm<EPI_BIAS>,      cudaFuncAttributeMaxDynamicSharedMemorySize, SMEM_BYTES);
    cudaFuncSetAttribute(tc_gemm<EPI_GELU>,      cudaFuncAttributeMaxDynamicSharedMemorySize, SMEM_BYTES);
    cudaFuncSetAttribute(tc_gemm<EPI_RES_LN2>,   cudaFuncAttributeMaxDynamicSharedMemorySize, SMEM_BYTES);
    cudaFuncSetAttribute(tc_gemm<EPI_BIAS_RESH>, cudaFuncAttributeMaxDynamicSharedMemorySize, SMEM_BYTES);
    cudaFuncSetAttribute(attn_kernel,            cudaFuncAttributeMaxDynamicSharedMemorySize, ATT_SMEM);

    const int MT = NTOK / 128;  // 784

    // 0. fused prep: weight->half + LN1->half
    prep_kernel<<<W_BLOCKS + LN_BLOCKS, 256>>>(qkv_w, proj_w, mlp_w1, mlp_w2, p_wTh,
                                               x, ln1_g, ln1_b, p_lnh);
    // 1. QKV = ln1 @ qkv_w + qkv_b  -> half
    tc_gemm<EPI_BIAS><<<dim3(3, MT), 256, SMEM_BYTES>>>(
        p_lnh, wt_qkv, qkv_b, nullptr, nullptr, nullptr, p_qkvh, 3 * CDIM, CDIM,
        nullptr, nullptr, nullptr);
    // 2. attention (tensor cores; one block per window)
    attn_kernel<<<NWIN, 256, ATT_SMEM>>>(p_qkvh, p_oh);
    // 3. x2 = x + proj(o) -> half ; fused LN2 -> half
    tc_gemm<EPI_RES_LN2><<<dim3(1, MT), 256, SMEM_BYTES>>>(
        p_oh, wt_proj, proj_b, x, nullptr, nullptr, p_x2h, CDIM, CDIM,
        ln2_g, ln2_b, p_lnh);
    // 4. h1 = gelu(ln2 @ w1 + b1) -> half
    tc_gemm<EPI_GELU><<<dim3(4, MT), 256, SMEM_BYTES>>>(
        p_lnh, wt_w1, mlp_b1, nullptr, nullptr, nullptr, p_h1h, HID, CDIM,
        nullptr, nullptr, nullptr);
    // 5. out = x2 + h1 @ w2 + b2  (fp32 out, half residual)
    tc_gemm<EPI_BIAS_RESH><<<dim3(1, MT), 256, SMEM_BYTES>>>(
        p_h1h, wt_w2, mlp_b2, nullptr, p_x2h, out, nullptr, CDIM, HID,
        nullptr, nullptr, nullptr);
}